// round 12
// baseline (speedup 1.0000x reference)
#include <cuda_runtime.h>
#include <cstddef>
#include <cstdint>

#define Bb   4
#define Ss   2048
#define DIN  512
#define Hh   8
#define DM   512
#define MROWS (Bb*Ss)          // 8192

// Scratch (device globals: allocation-free rule)
__device__ float g_Q [MROWS*DM];
__device__ float g_K [MROWS*DM];
__device__ float g_V [MROWS*DM];
__device__ float g_AO[MROWS*DM];
__device__ float g_P [MROWS*DIN];

// ===========================================================================
// helpers
// ===========================================================================
__device__ __forceinline__ uint32_t f2tf32(float f) {
    uint32_t r;
    asm("cvt.rna.tf32.f32 %0, %1;" : "=r"(r) : "f"(f));
    return r;
}

// D += A * B  (m16n8k8, tf32 inputs, fp32 accum). row.col.
__device__ __forceinline__ void mma_tf32(float* d, const uint32_t* a,
                                         uint32_t b0, uint32_t b1) {
    asm volatile(
        "mma.sync.aligned.m16n8k8.row.col.f32.tf32.tf32.f32 "
        "{%0,%1,%2,%3}, {%4,%5,%6,%7}, {%8,%9}, {%0,%1,%2,%3};"
        : "+f"(d[0]), "+f"(d[1]), "+f"(d[2]), "+f"(d[3])
        : "r"(a[0]), "r"(a[1]), "r"(a[2]), "r"(a[3]), "r"(b0), "r"(b1));
}

__device__ __forceinline__ void ldsm_x4(uint32_t* r, uint32_t addr) {
    asm volatile("ldmatrix.sync.aligned.m8n8.x4.shared.b16 {%0,%1,%2,%3}, [%4];"
                 : "=r"(r[0]), "=r"(r[1]), "=r"(r[2]), "=r"(r[3]) : "r"(addr));
}

// ===========================================================================
// Tensor-core GEMM, double-buffered smem, single barrier per k-step.
// BM=128, BN=128, BK=32, 256 threads, 2 CTAs/SM. 70KB dynamic smem.
// ===========================================================================
#define XS_STR 36
#define WS_STR 136
#define GEMM_BUF_FLOATS (128*XS_STR + 32*WS_STR)        // 8960
#define GEMM_SMEM_BYTES (2 * GEMM_BUF_FLOATS * 4)       // 71680

__global__ __launch_bounds__(256, 2)
void gemm_tc_kernel(const float* __restrict__ X, const float* __restrict__ W,
                    const float* __restrict__ bias, float* __restrict__ C) {
    extern __shared__ float gsm[];

    const int tid  = threadIdx.x;
    const int lane = tid & 31;
    const int wid  = tid >> 5;
    const int gid  = lane >> 2;
    const int tig  = lane & 3;

    const int warp_m = wid >> 2;
    const int warp_n = wid & 3;
    const int m_base = warp_m * 64;
    const int n_base = warp_n * 32;

    const int bm = blockIdx.x * 128;
    const int bn = blockIdx.y * 128;

    // per-thread staging coordinates (full-tile coverage, verified:
    // X: 256 thr x 16 floats = 4096 = 128x32 ; W: 256 x 16 = 4096 = 32x128)
    const int xr0 = tid >> 1;
    const int xc0 = (tid & 1) * 16;
    const int wr0 = tid >> 3;
    const int wc0 = (tid & 7) * 16;

    float4 xs0, xs1, xs2, xs3, ws0, ws1, ws2, ws3;

    auto ldg_tile = [&](int k0) {
        const float* xp = X + (size_t)(bm + xr0) * 512 + k0 + xc0;
        xs0 = *(const float4*)(xp);
        xs1 = *(const float4*)(xp + 4);
        xs2 = *(const float4*)(xp + 8);
        xs3 = *(const float4*)(xp + 12);
        const float* wp = W + (size_t)(k0 + wr0) * 512 + bn + wc0;
        ws0 = *(const float4*)(wp);
        ws1 = *(const float4*)(wp + 4);
        ws2 = *(const float4*)(wp + 8);
        ws3 = *(const float4*)(wp + 12);
    };
    auto sts_tile = [&](int buf) {
        float* Xs = gsm + buf * GEMM_BUF_FLOATS;
        float* Ws = Xs + 128 * XS_STR;
        uint4 t0 = { f2tf32(xs0.x), f2tf32(xs0.y), f2tf32(xs0.z), f2tf32(xs0.w) };
        uint4 t1 = { f2tf32(xs1.x), f2tf32(xs1.y), f2tf32(xs1.z), f2tf32(xs1.w) };
        uint4 t2 = { f2tf32(xs2.x), f2tf32(xs2.y), f2tf32(xs2.z), f2tf32(xs2.w) };
        uint4 t3 = { f2tf32(xs3.x), f2tf32(xs3.y), f2tf32(xs3.z), f2tf32(xs3.w) };
        *(uint4*)(Xs + xr0 * XS_STR + xc0)      = t0;
        *(uint4*)(Xs + xr0 * XS_STR + xc0 + 4)  = t1;
        *(uint4*)(Xs + xr0 * XS_STR + xc0 + 8)  = t2;
        *(uint4*)(Xs + xr0 * XS_STR + xc0 + 12) = t3;
        uint4 u0 = { f2tf32(ws0.x), f2tf32(ws0.y), f2tf32(ws0.z), f2tf32(ws0.w) };
        uint4 u1 = { f2tf32(ws1.x), f2tf32(ws1.y), f2tf32(ws1.z), f2tf32(ws1.w) };
        uint4 u2 = { f2tf32(ws2.x), f2tf32(ws2.y), f2tf32(ws2.z), f2tf32(ws2.w) };
        uint4 u3 = { f2tf32(ws3.x), f2tf32(ws3.y), f2tf32(ws3.z), f2tf32(ws3.w) };
        *(uint4*)(Ws + wr0 * WS_STR + wc0)      = u0;
        *(uint4*)(Ws + wr0 * WS_STR + wc0 + 4)  = u1;
        *(uint4*)(Ws + wr0 * WS_STR + wc0 + 8)  = u2;
        *(uint4*)(Ws + wr0 * WS_STR + wc0 + 12) = u3;
    };

    float acc[4][4][4];
    #pragma unroll
    for (int mf = 0; mf < 4; mf++)
        #pragma unroll
        for (int nf = 0; nf < 4; nf++)
            #pragma unroll
            for (int c = 0; c < 4; c++) acc[mf][nf][c] = 0.f;

    ldg_tile(0);
    sts_tile(0);
    __syncthreads();

    for (int it = 0; it < 16; it++) {
        const int buf = it & 1;
        const float* Xs = gsm + buf * GEMM_BUF_FLOATS;
        const float* Ws = Xs + 128 * XS_STR;

        if (it < 15) ldg_tile((it + 1) * 32);   // LDG latency hidden by MMAs

        #pragma unroll
        for (int ks = 0; ks < 4; ks++) {
            const int kk = ks * 8;
            uint32_t A[4][4];
            #pragma unroll
            for (int mf = 0; mf < 4; mf++) {
                const float* ap = Xs + (m_base + mf * 16 + gid) * XS_STR + kk + tig;
                A[mf][0] = __float_as_uint(ap[0]);
                A[mf][1] = __float_as_uint(ap[8 * XS_STR]);
                A[mf][2] = __float_as_uint(ap[4]);
                A[mf][3] = __float_as_uint(ap[8 * XS_STR + 4]);
            }
            #pragma unroll
            for (int nf = 0; nf < 4; nf++) {
                const float* bp = Ws + (kk + tig) * WS_STR + n_base + nf * 8 + gid;
                uint32_t b0 = __float_as_uint(bp[0]);
                uint32_t b1 = __float_as_uint(bp[4 * WS_STR]);
                #pragma unroll
                for (int mf = 0; mf < 4; mf++)
                    mma_tf32(acc[mf][nf], A[mf], b0, b1);
            }
        }

        if (it < 15) sts_tile(buf ^ 1);         // writes idle buffer: no race
        __syncthreads();
    }

    #pragma unroll
    for (int nf = 0; nf < 4; nf++) {
        const int col = bn + n_base + nf * 8 + 2 * tig;
        float2 b2 = *(const float2*)(bias + col);
        #pragma unroll
        for (int mf = 0; mf < 4; mf++) {
            const int row0 = bm + m_base + mf * 16 + gid;
            float2 o0 = { acc[mf][nf][0] + b2.x, acc[mf][nf][1] + b2.y };
            float2 o1 = { acc[mf][nf][2] + b2.x, acc[mf][nf][3] + b2.y };
            *(float2*)(C + (size_t)row0 * 512 + col) = o0;
            *(float2*)(C + (size_t)(row0 + 8) * 512 + col) = o1;
        }
    }
}

// ===========================================================================
// mma.sync tf32 flash attention, v5: fixed-max softmax (no running max,
// no O rescale, sum-reduce overlapped with PV MMAs). Otherwise = proven v4.
// ===========================================================================
#define KSTR 68
#define VSTR 72
#define SM_K0 0
#define SM_K1 (32*KSTR)
#define SM_V0 (2*32*KSTR)
#define SM_V1 (SM_V0 + 32*VSTR)
#define ATTN_SMEM_FLOATS (SM_V0 + 2*32*VSTR)   // 8960 floats = 35840 B
#define SMAX 8.0f

__global__ __launch_bounds__(128, 2)
void attn_mma_kernel(const float* __restrict__ Qg, const float* __restrict__ Kg,
                     const float* __restrict__ Vg, const float* __restrict__ mask,
                     float* __restrict__ AO) {
    __shared__ float sm[ATTN_SMEM_FLOATS];
    const int tid  = threadIdx.x;
    const int lane = tid & 31;
    const int wid  = tid >> 5;        // 0..3
    const int gid  = lane >> 2;
    const int tig  = lane & 3;
    const int srcA = (lane & ~3) | (tig >> 1);
    const int srcB = srcA + 2;
    const bool odd = (tig & 1);

    const int lm_base = (lane & 7) * KSTR + ((lane >> 3) & 1) * 4 + (lane >> 4) * 8;
    const uint32_t smK0_u = (uint32_t)__cvta_generic_to_shared(sm + SM_K0);
    const uint32_t smK1_u = (uint32_t)__cvta_generic_to_shared(sm + SM_K1);

    const int bh = blockIdx.y;
    const int b  = bh >> 3;
    const int h  = bh & 7;
    const int q0 = blockIdx.x * 128;

    const float* Kb = Kg + (size_t)b * Ss * 512 + h * 64;
    const float* Vb = Vg + (size_t)b * Ss * 512 + h * 64;

    const int qrow0 = q0 + wid * 32 + gid;
    const int qrow1 = qrow0 + 16;
    uint32_t Qa[2][8][4];
    #pragma unroll
    for (int mf = 0; mf < 2; mf++) {
        const float* Qp = Qg + ((size_t)b * Ss + (mf ? qrow1 : qrow0)) * 512 + h * 64;
        #pragma unroll
        for (int ch = 0; ch < 8; ch++) {
            Qa[mf][ch][0] = f2tf32(Qp[ch * 8 + tig] * 0.125f);
            Qa[mf][ch][1] = f2tf32(Qp[8 * 512 + ch * 8 + tig] * 0.125f);
            Qa[mf][ch][2] = f2tf32(Qp[ch * 8 + tig + 4] * 0.125f);
            Qa[mf][ch][3] = f2tf32(Qp[8 * 512 + ch * 8 + tig + 4] * 0.125f);
        }
    }

    auto load_kv = [&](int k0, int sel) {
        float* Ks = sm + (sel ? SM_K1 : SM_K0);
        float* Vs = sm + (sel ? SM_V1 : SM_V0);
        #pragma unroll
        for (int l = 0; l < 4; l++) {
            int e = tid + l * 128;
            int r = e >> 4, c4 = e & 15;
            float4 kv = *(const float4*)(Kb + (size_t)(k0 + r) * 512 + c4 * 4);
            uint4 tk = { f2tf32(kv.x), f2tf32(kv.y), f2tf32(kv.z), f2tf32(kv.w) };
            *(uint4*)(Ks + r * KSTR + c4 * 4) = tk;
            float4 vv = *(const float4*)(Vb + (size_t)(k0 + r) * 512 + c4 * 4);
            uint4 tv = { f2tf32(vv.x), f2tf32(vv.y), f2tf32(vv.z), f2tf32(vv.w) };
            *(uint4*)(Vs + r * VSTR + c4 * 4) = tv;
        }
    };

    load_kv(0, 0);

    const float* Mr[4];
    Mr[0] = mask + (size_t)b * Ss * Ss + (size_t)qrow0 * Ss;
    Mr[1] = Mr[0] + (size_t)8 * Ss;
    Mr[2] = mask + (size_t)b * Ss * Ss + (size_t)qrow1 * Ss;
    Mr[3] = Mr[2] + (size_t)8 * Ss;

    float lI[4] = {0.f, 0.f, 0.f, 0.f};
    float O[2][8][4];
    #pragma unroll
    for (int mf = 0; mf < 2; mf++)
        #pragma unroll
        for (int j = 0; j < 8; j++)
            #pragma unroll
            for (int c = 0; c < 4; c++) O[mf][j][c] = 0.f;

    __syncthreads();

    for (int kt = 0; kt < 64; kt++) {
        const int sel = kt & 1;
        const int k0  = kt * 32;
        const float* Vs = sm + (sel ? SM_V1 : SM_V0);
        const uint32_t smK_u = sel ? smK1_u : smK0_u;

        float2 mk[4][4];
        #pragma unroll
        for (int r = 0; r < 4; r++)
            #pragma unroll
            for (int kf = 0; kf < 4; kf++)
                mk[r][kf] = *(const float2*)(Mr[r] + k0 + kf * 8 + 2 * tig);

        float S[2][4][4];
        #pragma unroll
        for (int mf = 0; mf < 2; mf++)
            #pragma unroll
            for (int kf = 0; kf < 4; kf++)
                #pragma unroll
                for (int c = 0; c < 4; c++) S[mf][kf][c] = 0.f;

        #pragma unroll
        for (int kf = 0; kf < 4; kf++) {
            #pragma unroll
            for (int ch2 = 0; ch2 < 4; ch2++) {
                uint32_t r[4];
                ldsm_x4(r, smK_u + 4u * (uint32_t)(kf * 8 * KSTR + ch2 * 16 + lm_base));
                mma_tf32(S[0][kf], Qa[0][2 * ch2],     r[0], r[1]);
                mma_tf32(S[0][kf], Qa[0][2 * ch2 + 1], r[2], r[3]);
                mma_tf32(S[1][kf], Qa[1][2 * ch2],     r[0], r[1]);
                mma_tf32(S[1][kf], Qa[1][2 * ch2 + 1], r[2], r[3]);
            }
        }

        if (kt < 63) load_kv(k0 + 32, sel ^ 1);

        // ---- mask * s, threshold, fixed-max exp (no row-max machinery) ----
        float tsum[4] = {0.f, 0.f, 0.f, 0.f};
        #pragma unroll
        for (int mf = 0; mf < 2; mf++) {
            const int rA = mf * 2, rB = mf * 2 + 1;
            #pragma unroll
            for (int kf = 0; kf < 4; kf++) {
                float s0 = S[mf][kf][0] * mk[rA][kf].x;
                float s1 = S[mf][kf][1] * mk[rA][kf].y;
                float s2 = S[mf][kf][2] * mk[rB][kf].x;
                float s3 = S[mf][kf][3] * mk[rB][kf].y;
                s0 = (s0 > 0.f) ? fminf(s0, 80.f) : -10000.f;
                s1 = (s1 > 0.f) ? fminf(s1, 80.f) : -10000.f;
                s2 = (s2 > 0.f) ? fminf(s2, 80.f) : -10000.f;
                s3 = (s3 > 0.f) ? fminf(s3, 80.f) : -10000.f;
                float p0 = __expf(s0 - SMAX);
                float p1 = __expf(s1 - SMAX);
                float p2 = __expf(s2 - SMAX);
                float p3 = __expf(s3 - SMAX);
                tsum[rA] += p0 + p1;
                tsum[rB] += p2 + p3;
                S[mf][kf][0] = __uint_as_float(f2tf32(p0));
                S[mf][kf][1] = __uint_as_float(f2tf32(p1));
                S[mf][kf][2] = __uint_as_float(f2tf32(p2));
                S[mf][kf][3] = __uint_as_float(f2tf32(p3));
            }
        }

        // ---- O += P @ V (A-frags via quad shuffle transpose) ----
        #pragma unroll
        for (int kc = 0; kc < 4; kc++) {
            uint32_t A[2][4];
            #pragma unroll
            for (int mf = 0; mf < 2; mf++) {
                float x0 = __shfl_sync(0xffffffffu, S[mf][kc][0], srcA);
                float x1 = __shfl_sync(0xffffffffu, S[mf][kc][1], srcA);
                float y0 = __shfl_sync(0xffffffffu, S[mf][kc][2], srcA);
                float y1 = __shfl_sync(0xffffffffu, S[mf][kc][3], srcA);
                float z0 = __shfl_sync(0xffffffffu, S[mf][kc][0], srcB);
                float z1 = __shfl_sync(0xffffffffu, S[mf][kc][1], srcB);
                float w0 = __shfl_sync(0xffffffffu, S[mf][kc][2], srcB);
                float w1 = __shfl_sync(0xffffffffu, S[mf][kc][3], srcB);
                A[mf][0] = __float_as_uint(odd ? x1 : x0);
                A[mf][1] = __float_as_uint(odd ? y1 : y0);
                A[mf][2] = __float_as_uint(odd ? z1 : z0);
                A[mf][3] = __float_as_uint(odd ? w1 : w0);
            }
            #pragma unroll
            for (int df = 0; df < 8; df++) {
                const float* vp = Vs + (kc * 8 + tig) * VSTR + df * 8 + gid;
                uint32_t b0 = __float_as_uint(vp[0]);
                uint32_t b1 = __float_as_uint(vp[4 * VSTR]);
                mma_tf32(O[0][df], A[0], b0, b1);
                mma_tf32(O[1][df], A[1], b0, b1);
            }
        }

        // ---- sum reductions overlap the PV MMA tail ----
        #pragma unroll
        for (int r = 0; r < 4; r++) {
            float s = tsum[r];
            s += __shfl_xor_sync(0xffffffffu, s, 1);
            s += __shfl_xor_sync(0xffffffffu, s, 2);
            lI[r] += s;
        }

        __syncthreads();
    }

    #pragma unroll
    for (int mf = 0; mf < 2; mf++) {
        const int rA = mf * 2, rB = mf * 2 + 1;
        const float inv0 = 1.f / lI[rA];
        const float inv1 = 1.f / lI[rB];
        float* Op0 = AO + ((size_t)b * Ss + (mf ? qrow1 : qrow0)) * 512 + h * 64;
        float* Op1 = Op0 + (size_t)8 * 512;
        #pragma unroll
        for (int df = 0; df < 8; df++) {
            float2 o0 = { O[mf][df][0] * inv0, O[mf][df][1] * inv0 };
            float2 o1 = { O[mf][df][2] * inv1, O[mf][df][3] * inv1 };
            *(float2*)(Op0 + df * 8 + 2 * tig) = o0;
            *(float2*)(Op1 + df * 8 + 2 * tig) = o1;
        }
    }
}

// ===========================================================================
// Residual + LayerNorm: 128 threads x float4 per 512-wide row (proven R10).
// ===========================================================================
__global__ __launch_bounds__(128)
void ln_kernel(const float* __restrict__ q, const float* __restrict__ gamma,
               const float* __restrict__ beta, float* __restrict__ out) {
    __shared__ float rs[4], rs2[4];
    const int r = blockIdx.x;
    const int j = threadIdx.x;          // 0..127
    const int w = j >> 5, ln = j & 31;

    float4 qv = *(const float4*)(q + (size_t)r * 512 + j * 4);
    float4 pv = *(const float4*)(g_P + (size_t)r * 512 + j * 4);
    float4 v  = { qv.x + pv.x, qv.y + pv.y, qv.z + pv.z, qv.w + pv.w };

    float s  = v.x + v.y + v.z + v.w;
    float s2 = v.x * v.x + v.y * v.y + v.z * v.z + v.w * v.w;
    #pragma unroll
    for (int o = 16; o > 0; o >>= 1) {
        s  += __shfl_xor_sync(0xffffffffu, s,  o);
        s2 += __shfl_xor_sync(0xffffffffu, s2, o);
    }
    if (ln == 0) { rs[w] = s; rs2[w] = s2; }
    __syncthreads();
    s  = rs[0]  + rs[1]  + rs[2]  + rs[3];
    s2 = rs2[0] + rs2[1] + rs2[2] + rs2[3];

    const float mu  = s * (1.f / 512.f);
    const float var = s2 * (1.f / 512.f) - mu * mu;
    const float inv = rsqrtf(var + 1e-5f);

    float4 g4 = *(const float4*)(gamma + j * 4);
    float4 b4 = *(const float4*)(beta + j * 4);
    float4 o;
    o.x = (v.x - mu) * inv * g4.x + b4.x;
    o.y = (v.y - mu) * inv * g4.y + b4.y;
    o.z = (v.z - mu) * inv * g4.z + b4.z;
    o.w = (v.w - mu) * inv * g4.w + b4.w;
    *(float4*)(out + (size_t)r * 512 + j * 4) = o;
}

// ===========================================================================
extern "C" void kernel_launch(void* const* d_in, const int* in_sizes, int n_in,
                              void* d_out, int out_size) {
    const float* q     = (const float*)d_in[0];
    const float* k     = (const float*)d_in[1];
    const float* v     = (const float*)d_in[2];
    const float* mask  = (const float*)d_in[3];
    const float* Wq    = (const float*)d_in[4];
    const float* bq    = (const float*)d_in[5];
    const float* Wk    = (const float*)d_in[6];
    const float* bk    = (const float*)d_in[7];
    const float* Wv    = (const float*)d_in[8];
    const float* bv    = (const float*)d_in[9];
    const float* Wo    = (const float*)d_in[10];
    const float* bo    = (const float*)d_in[11];
    const float* gamma = (const float*)d_in[12];
    const float* beta  = (const float*)d_in[13];
    float* out = (float*)d_out;

    float *gQ, *gK, *gV, *gAO, *gP;
    cudaGetSymbolAddress((void**)&gQ,  g_Q);
    cudaGetSymbolAddress((void**)&gK,  g_K);
    cudaGetSymbolAddress((void**)&gV,  g_V);
    cudaGetSymbolAddress((void**)&gAO, g_AO);
    cudaGetSymbolAddress((void**)&gP,  g_P);

    static bool attr_set = false;
    if (!attr_set) {
        cudaFuncSetAttribute(gemm_tc_kernel,
                             cudaFuncAttributeMaxDynamicSharedMemorySize,
                             GEMM_SMEM_BYTES);
        attr_set = true;
    }

    dim3 gg(MROWS / 128, 512 / 128);
    gemm_tc_kernel<<<gg, 256, GEMM_SMEM_BYTES>>>(q, Wq, bq, gQ);
    gemm_tc_kernel<<<gg, 256, GEMM_SMEM_BYTES>>>(k, Wk, bk, gK);
    gemm_tc_kernel<<<gg, 256, GEMM_SMEM_BYTES>>>(v, Wv, bv, gV);

    attn_mma_kernel<<<dim3(Ss / 128, Bb * Hh), 128>>>(gQ, gK, gV, mask, gAO);

    gemm_tc_kernel<<<gg, 256, GEMM_SMEM_BYTES>>>(gAO, Wo, bo, gP);

    ln_kernel<<<MROWS, 128>>>(q, gamma, beta, out);
}

// round 13
// speedup vs baseline: 1.1908x; 1.1908x over previous
#include <cuda_runtime.h>
#include <cstddef>
#include <cstdint>

#define Bb   4
#define Ss   2048
#define DIN  512
#define Hh   8
#define DM   512
#define MROWS (Bb*Ss)          // 8192

// Scratch (device globals: allocation-free rule)
__device__ float g_Q [MROWS*DM];
__device__ float g_K [MROWS*DM];
__device__ float g_V [MROWS*DM];
__device__ float g_AO[MROWS*DM];
__device__ float g_P [MROWS*DIN];

// ===========================================================================
// helpers
// ===========================================================================
__device__ __forceinline__ uint32_t f2tf32(float f) {
    uint32_t r;
    asm("cvt.rna.tf32.f32 %0, %1;" : "=r"(r) : "f"(f));
    return r;
}

// D += A * B  (m16n8k8, tf32 inputs, fp32 accum). row.col.
__device__ __forceinline__ void mma_tf32(float* d, const uint32_t* a,
                                         uint32_t b0, uint32_t b1) {
    asm volatile(
        "mma.sync.aligned.m16n8k8.row.col.f32.tf32.tf32.f32 "
        "{%0,%1,%2,%3}, {%4,%5,%6,%7}, {%8,%9}, {%0,%1,%2,%3};"
        : "+f"(d[0]), "+f"(d[1]), "+f"(d[2]), "+f"(d[3])
        : "r"(a[0]), "r"(a[1]), "r"(a[2]), "r"(a[3]), "r"(b0), "r"(b1));
}

__device__ __forceinline__ void ldsm_x4(uint32_t* r, uint32_t addr) {
    asm volatile("ldmatrix.sync.aligned.m8n8.x4.shared.b16 {%0,%1,%2,%3}, [%4];"
                 : "=r"(r[0]), "=r"(r[1]), "=r"(r[2]), "=r"(r[3]) : "r"(addr));
}

// ===========================================================================
// Tensor-core GEMM (proven R5/R8/R11 body). gridDim.z selects one of up to
// 3 independent (X, W, bias, C) problem instances -> QKV in ONE launch.
// ===========================================================================
#define XS_STR 36
#define WS_STR 136

__global__ __launch_bounds__(256)
void gemm_tc_kernel(const float* __restrict__ X0, const float* __restrict__ X1,
                    const float* __restrict__ X2,
                    const float* __restrict__ W0, const float* __restrict__ W1,
                    const float* __restrict__ W2,
                    const float* __restrict__ b0p, const float* __restrict__ b1p,
                    const float* __restrict__ b2p,
                    float* __restrict__ C0, float* __restrict__ C1,
                    float* __restrict__ C2) {
    __shared__ float Xs[128 * XS_STR];
    __shared__ float Ws[32 * WS_STR];

    const int z = blockIdx.z;
    const float* X    = (z == 0) ? X0 : (z == 1) ? X1 : X2;
    const float* W    = (z == 0) ? W0 : (z == 1) ? W1 : W2;
    const float* bias = (z == 0) ? b0p : (z == 1) ? b1p : b2p;
    float*       C    = (z == 0) ? C0 : (z == 1) ? C1 : C2;

    const int tid  = threadIdx.x;
    const int lane = tid & 31;
    const int wid  = tid >> 5;
    const int gid  = lane >> 2;
    const int tig  = lane & 3;

    const int warp_m = wid >> 2;
    const int warp_n = wid & 3;
    const int m_base = warp_m * 64;
    const int n_base = warp_n * 32;

    const int bm = blockIdx.x * 128;
    const int bn = blockIdx.y * 128;

    float acc[4][4][4];
    #pragma unroll
    for (int mf = 0; mf < 4; mf++)
        #pragma unroll
        for (int nf = 0; nf < 4; nf++)
            #pragma unroll
            for (int c = 0; c < 4; c++) acc[mf][nf][c] = 0.f;

    for (int k0 = 0; k0 < 512; k0 += 32) {
        #pragma unroll
        for (int l = 0; l < 4; l++) {
            int e = tid + l * 256;
            int r = e >> 3, c4 = e & 7;
            float4 v = *(const float4*)(X + (size_t)(bm + r) * 512 + k0 + c4 * 4);
            uint4 t = { f2tf32(v.x), f2tf32(v.y), f2tf32(v.z), f2tf32(v.w) };
            *(uint4*)(Xs + r * XS_STR + c4 * 4) = t;
        }
        #pragma unroll
        for (int l = 0; l < 4; l++) {
            int e = tid + l * 256;
            int r = e >> 5, c4 = e & 31;
            float4 v = *(const float4*)(W + (size_t)(k0 + r) * 512 + bn + c4 * 4);
            uint4 t = { f2tf32(v.x), f2tf32(v.y), f2tf32(v.z), f2tf32(v.w) };
            *(uint4*)(Ws + r * WS_STR + c4 * 4) = t;
        }
        __syncthreads();

        #pragma unroll
        for (int ks = 0; ks < 4; ks++) {
            const int kk = ks * 8;
            uint32_t A[4][4];
            #pragma unroll
            for (int mf = 0; mf < 4; mf++) {
                const float* ap = Xs + (m_base + mf * 16 + gid) * XS_STR + kk + tig;
                A[mf][0] = __float_as_uint(ap[0]);
                A[mf][1] = __float_as_uint(ap[8 * XS_STR]);
                A[mf][2] = __float_as_uint(ap[4]);
                A[mf][3] = __float_as_uint(ap[8 * XS_STR + 4]);
            }
            #pragma unroll
            for (int nf = 0; nf < 4; nf++) {
                const float* bp = Ws + (kk + tig) * WS_STR + n_base + nf * 8 + gid;
                uint32_t bb0 = __float_as_uint(bp[0]);
                uint32_t bb1 = __float_as_uint(bp[4 * WS_STR]);
                #pragma unroll
                for (int mf = 0; mf < 4; mf++)
                    mma_tf32(acc[mf][nf], A[mf], bb0, bb1);
            }
        }
        __syncthreads();
    }

    #pragma unroll
    for (int nf = 0; nf < 4; nf++) {
        const int col = bn + n_base + nf * 8 + 2 * tig;
        float2 b2 = *(const float2*)(bias + col);
        #pragma unroll
        for (int mf = 0; mf < 4; mf++) {
            const int row0 = bm + m_base + mf * 16 + gid;
            float2 o0 = { acc[mf][nf][0] + b2.x, acc[mf][nf][1] + b2.y };
            float2 o1 = { acc[mf][nf][2] + b2.x, acc[mf][nf][3] + b2.y };
            *(float2*)(C + (size_t)row0 * 512 + col) = o0;
            *(float2*)(C + (size_t)(row0 + 8) * 512 + col) = o1;
        }
    }
}

// ===========================================================================
// mma.sync tf32 flash attention, v4 (proven R8/R11 version, unchanged).
// ===========================================================================
#define KSTR 68
#define VSTR 72
#define SM_K0 0
#define SM_K1 (32*KSTR)
#define SM_V0 (2*32*KSTR)
#define SM_V1 (SM_V0 + 32*VSTR)
#define ATTN_SMEM_FLOATS (SM_V0 + 2*32*VSTR)   // 8960 floats = 35840 B

__global__ __launch_bounds__(128, 2)
void attn_mma_kernel(const float* __restrict__ Qg, const float* __restrict__ Kg,
                     const float* __restrict__ Vg, const float* __restrict__ mask,
                     float* __restrict__ AO) {
    __shared__ float sm[ATTN_SMEM_FLOATS];
    const int tid  = threadIdx.x;
    const int lane = tid & 31;
    const int wid  = tid >> 5;        // 0..3
    const int gid  = lane >> 2;
    const int tig  = lane & 3;
    const int srcA = (lane & ~3) | (tig >> 1);
    const int srcB = srcA + 2;
    const bool odd = (tig & 1);

    const int lm_base = (lane & 7) * KSTR + ((lane >> 3) & 1) * 4 + (lane >> 4) * 8;
    const uint32_t smK0_u = (uint32_t)__cvta_generic_to_shared(sm + SM_K0);
    const uint32_t smK1_u = (uint32_t)__cvta_generic_to_shared(sm + SM_K1);

    const int bh = blockIdx.y;
    const int b  = bh >> 3;
    const int h  = bh & 7;
    const int q0 = blockIdx.x * 128;

    const float* Kb = Kg + (size_t)b * Ss * 512 + h * 64;
    const float* Vb = Vg + (size_t)b * Ss * 512 + h * 64;

    const int qrow0 = q0 + wid * 32 + gid;
    const int qrow1 = qrow0 + 16;
    uint32_t Qa[2][8][4];
    #pragma unroll
    for (int mf = 0; mf < 2; mf++) {
        const float* Qp = Qg + ((size_t)b * Ss + (mf ? qrow1 : qrow0)) * 512 + h * 64;
        #pragma unroll
        for (int ch = 0; ch < 8; ch++) {
            Qa[mf][ch][0] = f2tf32(Qp[ch * 8 + tig] * 0.125f);
            Qa[mf][ch][1] = f2tf32(Qp[8 * 512 + ch * 8 + tig] * 0.125f);
            Qa[mf][ch][2] = f2tf32(Qp[ch * 8 + tig + 4] * 0.125f);
            Qa[mf][ch][3] = f2tf32(Qp[8 * 512 + ch * 8 + tig + 4] * 0.125f);
        }
    }

    auto load_kv = [&](int k0, int sel) {
        float* Ks = sm + (sel ? SM_K1 : SM_K0);
        float* Vs = sm + (sel ? SM_V1 : SM_V0);
        #pragma unroll
        for (int l = 0; l < 4; l++) {
            int e = tid + l * 128;
            int r = e >> 4, c4 = e & 15;
            float4 kv = *(const float4*)(Kb + (size_t)(k0 + r) * 512 + c4 * 4);
            uint4 tk = { f2tf32(kv.x), f2tf32(kv.y), f2tf32(kv.z), f2tf32(kv.w) };
            *(uint4*)(Ks + r * KSTR + c4 * 4) = tk;
            float4 vv = *(const float4*)(Vb + (size_t)(k0 + r) * 512 + c4 * 4);
            uint4 tv = { f2tf32(vv.x), f2tf32(vv.y), f2tf32(vv.z), f2tf32(vv.w) };
            *(uint4*)(Vs + r * VSTR + c4 * 4) = tv;
        }
    };

    load_kv(0, 0);

    const float* Mr[4];
    Mr[0] = mask + (size_t)b * Ss * Ss + (size_t)qrow0 * Ss;
    Mr[1] = Mr[0] + (size_t)8 * Ss;
    Mr[2] = mask + (size_t)b * Ss * Ss + (size_t)qrow1 * Ss;
    Mr[3] = Mr[2] + (size_t)8 * Ss;

    float mI[4] = {-1e30f, -1e30f, -1e30f, -1e30f};
    float lI[4] = {0.f, 0.f, 0.f, 0.f};
    float O[2][8][4];
    #pragma unroll
    for (int mf = 0; mf < 2; mf++)
        #pragma unroll
        for (int j = 0; j < 8; j++)
            #pragma unroll
            for (int c = 0; c < 4; c++) O[mf][j][c] = 0.f;

    __syncthreads();

    for (int kt = 0; kt < 64; kt++) {
        const int sel = kt & 1;
        const int k0  = kt * 32;
        const float* Vs = sm + (sel ? SM_V1 : SM_V0);
        const uint32_t smK_u = sel ? smK1_u : smK0_u;

        float2 mk[4][4];
        #pragma unroll
        for (int r = 0; r < 4; r++)
            #pragma unroll
            for (int kf = 0; kf < 4; kf++)
                mk[r][kf] = *(const float2*)(Mr[r] + k0 + kf * 8 + 2 * tig);

        float S[2][4][4];
        #pragma unroll
        for (int mf = 0; mf < 2; mf++)
            #pragma unroll
            for (int kf = 0; kf < 4; kf++)
                #pragma unroll
                for (int c = 0; c < 4; c++) S[mf][kf][c] = 0.f;

        #pragma unroll
        for (int kf = 0; kf < 4; kf++) {
            #pragma unroll
            for (int ch2 = 0; ch2 < 4; ch2++) {
                uint32_t r[4];
                ldsm_x4(r, smK_u + 4u * (uint32_t)(kf * 8 * KSTR + ch2 * 16 + lm_base));
                mma_tf32(S[0][kf], Qa[0][2 * ch2],     r[0], r[1]);
                mma_tf32(S[0][kf], Qa[0][2 * ch2 + 1], r[2], r[3]);
                mma_tf32(S[1][kf], Qa[1][2 * ch2],     r[0], r[1]);
                mma_tf32(S[1][kf], Qa[1][2 * ch2 + 1], r[2], r[3]);
            }
        }

        if (kt < 63) load_kv(k0 + 32, sel ^ 1);

        #pragma unroll
        for (int mf = 0; mf < 2; mf++) {
            const int rA = mf * 2, rB = mf * 2 + 1;
            float mx0 = mI[rA], mx1 = mI[rB];
            #pragma unroll
            for (int kf = 0; kf < 4; kf++) {
                float s0 = S[mf][kf][0] * mk[rA][kf].x;
                float s1 = S[mf][kf][1] * mk[rA][kf].y;
                float s2 = S[mf][kf][2] * mk[rB][kf].x;
                float s3 = S[mf][kf][3] * mk[rB][kf].y;
                s0 = (s0 > 0.f) ? s0 : -10000.f;
                s1 = (s1 > 0.f) ? s1 : -10000.f;
                s2 = (s2 > 0.f) ? s2 : -10000.f;
                s3 = (s3 > 0.f) ? s3 : -10000.f;
                S[mf][kf][0] = s0; S[mf][kf][1] = s1;
                S[mf][kf][2] = s2; S[mf][kf][3] = s3;
                mx0 = fmaxf(mx0, fmaxf(s0, s1));
                mx1 = fmaxf(mx1, fmaxf(s2, s3));
            }
            mx0 = fmaxf(mx0, __shfl_xor_sync(0xffffffffu, mx0, 1));
            mx0 = fmaxf(mx0, __shfl_xor_sync(0xffffffffu, mx0, 2));
            mx1 = fmaxf(mx1, __shfl_xor_sync(0xffffffffu, mx1, 1));
            mx1 = fmaxf(mx1, __shfl_xor_sync(0xffffffffu, mx1, 2));

            float f0 = __expf(mI[rA] - mx0);
            float f1 = __expf(mI[rB] - mx1);
            float sum0 = 0.f, sum1 = 0.f;
            #pragma unroll
            for (int kf = 0; kf < 4; kf++) {
                float p0 = __expf(S[mf][kf][0] - mx0);
                float p1 = __expf(S[mf][kf][1] - mx0);
                float p2 = __expf(S[mf][kf][2] - mx1);
                float p3 = __expf(S[mf][kf][3] - mx1);
                sum0 += p0 + p1;
                sum1 += p2 + p3;
                S[mf][kf][0] = __uint_as_float(f2tf32(p0));
                S[mf][kf][1] = __uint_as_float(f2tf32(p1));
                S[mf][kf][2] = __uint_as_float(f2tf32(p2));
                S[mf][kf][3] = __uint_as_float(f2tf32(p3));
            }
            sum0 += __shfl_xor_sync(0xffffffffu, sum0, 1);
            sum0 += __shfl_xor_sync(0xffffffffu, sum0, 2);
            sum1 += __shfl_xor_sync(0xffffffffu, sum1, 1);
            sum1 += __shfl_xor_sync(0xffffffffu, sum1, 2);

            lI[rA] = lI[rA] * f0 + sum0;  mI[rA] = mx0;
            lI[rB] = lI[rB] * f1 + sum1;  mI[rB] = mx1;

            #pragma unroll
            for (int j = 0; j < 8; j++) {
                O[mf][j][0] *= f0; O[mf][j][1] *= f0;
                O[mf][j][2] *= f1; O[mf][j][3] *= f1;
            }
        }

        #pragma unroll
        for (int kc = 0; kc < 4; kc++) {
            uint32_t A[2][4];
            #pragma unroll
            for (int mf = 0; mf < 2; mf++) {
                float x0 = __shfl_sync(0xffffffffu, S[mf][kc][0], srcA);
                float x1 = __shfl_sync(0xffffffffu, S[mf][kc][1], srcA);
                float y0 = __shfl_sync(0xffffffffu, S[mf][kc][2], srcA);
                float y1 = __shfl_sync(0xffffffffu, S[mf][kc][3], srcA);
                float z0 = __shfl_sync(0xffffffffu, S[mf][kc][0], srcB);
                float z1 = __shfl_sync(0xffffffffu, S[mf][kc][1], srcB);
                float w0 = __shfl_sync(0xffffffffu, S[mf][kc][2], srcB);
                float w1 = __shfl_sync(0xffffffffu, S[mf][kc][3], srcB);
                A[mf][0] = __float_as_uint(odd ? x1 : x0);
                A[mf][1] = __float_as_uint(odd ? y1 : y0);
                A[mf][2] = __float_as_uint(odd ? z1 : z0);
                A[mf][3] = __float_as_uint(odd ? w1 : w0);
            }
            #pragma unroll
            for (int df = 0; df < 8; df++) {
                const float* vp = Vs + (kc * 8 + tig) * VSTR + df * 8 + gid;
                uint32_t b0 = __float_as_uint(vp[0]);
                uint32_t b1 = __float_as_uint(vp[4 * VSTR]);
                mma_tf32(O[0][df], A[0], b0, b1);
                mma_tf32(O[1][df], A[1], b0, b1);
            }
        }

        __syncthreads();
    }

    #pragma unroll
    for (int mf = 0; mf < 2; mf++) {
        const int rA = mf * 2, rB = mf * 2 + 1;
        const float inv0 = 1.f / lI[rA];
        const float inv1 = 1.f / lI[rB];
        float* Op0 = AO + ((size_t)b * Ss + (mf ? qrow1 : qrow0)) * 512 + h * 64;
        float* Op1 = Op0 + (size_t)8 * 512;
        #pragma unroll
        for (int df = 0; df < 8; df++) {
            float2 o0 = { O[mf][df][0] * inv0, O[mf][df][1] * inv0 };
            float2 o1 = { O[mf][df][2] * inv1, O[mf][df][3] * inv1 };
            *(float2*)(Op0 + df * 8 + 2 * tig) = o0;
            *(float2*)(Op1 + df * 8 + 2 * tig) = o1;
        }
    }
}

// ===========================================================================
// Residual + LayerNorm: 128 threads x float4 per 512-wide row (proven R10).
// ===========================================================================
__global__ __launch_bounds__(128)
void ln_kernel(const float* __restrict__ q, const float* __restrict__ gamma,
               const float* __restrict__ beta, float* __restrict__ out) {
    __shared__ float rs[4], rs2[4];
    const int r = blockIdx.x;
    const int j = threadIdx.x;          // 0..127
    const int w = j >> 5, ln = j & 31;

    float4 qv = *(const float4*)(q + (size_t)r * 512 + j * 4);
    float4 pv = *(const float4*)(g_P + (size_t)r * 512 + j * 4);
    float4 v  = { qv.x + pv.x, qv.y + pv.y, qv.z + pv.z, qv.w + pv.w };

    float s  = v.x + v.y + v.z + v.w;
    float s2 = v.x * v.x + v.y * v.y + v.z * v.z + v.w * v.w;
    #pragma unroll
    for (int o = 16; o > 0; o >>= 1) {
        s  += __shfl_xor_sync(0xffffffffu, s,  o);
        s2 += __shfl_xor_sync(0xffffffffu, s2, o);
    }
    if (ln == 0) { rs[w] = s; rs2[w] = s2; }
    __syncthreads();
    s  = rs[0]  + rs[1]  + rs[2]  + rs[3];
    s2 = rs2[0] + rs2[1] + rs2[2] + rs2[3];

    const float mu  = s * (1.f / 512.f);
    const float var = s2 * (1.f / 512.f) - mu * mu;
    const float inv = rsqrtf(var + 1e-5f);

    float4 g4 = *(const float4*)(gamma + j * 4);
    float4 b4 = *(const float4*)(beta + j * 4);
    float4 o;
    o.x = (v.x - mu) * inv * g4.x + b4.x;
    o.y = (v.y - mu) * inv * g4.y + b4.y;
    o.z = (v.z - mu) * inv * g4.z + b4.z;
    o.w = (v.w - mu) * inv * g4.w + b4.w;
    *(float4*)(out + (size_t)r * 512 + j * 4) = o;
}

// ===========================================================================
extern "C" void kernel_launch(void* const* d_in, const int* in_sizes, int n_in,
                              void* d_out, int out_size) {
    const float* q     = (const float*)d_in[0];
    const float* k     = (const float*)d_in[1];
    const float* v     = (const float*)d_in[2];
    const float* mask  = (const float*)d_in[3];
    const float* Wq    = (const float*)d_in[4];
    const float* bq    = (const float*)d_in[5];
    const float* Wk    = (const float*)d_in[6];
    const float* bk    = (const float*)d_in[7];
    const float* Wv    = (const float*)d_in[8];
    const float* bv    = (const float*)d_in[9];
    const float* Wo    = (const float*)d_in[10];
    const float* bo    = (const float*)d_in[11];
    const float* gamma = (const float*)d_in[12];
    const float* beta  = (const float*)d_in[13];
    float* out = (float*)d_out;

    float *gQ, *gK, *gV, *gAO, *gP;
    cudaGetSymbolAddress((void**)&gQ,  g_Q);
    cudaGetSymbolAddress((void**)&gK,  g_K);
    cudaGetSymbolAddress((void**)&gV,  g_V);
    cudaGetSymbolAddress((void**)&gAO, g_AO);
    cudaGetSymbolAddress((void**)&gP,  g_P);

    // QKV projections fused into one launch (z = 0,1,2)
    dim3 gqkv(MROWS / 128, 512 / 128, 3);
    gemm_tc_kernel<<<gqkv, 256>>>(q, k, v, Wq, Wk, Wv, bq, bk, bv, gQ, gK, gV);

    attn_mma_kernel<<<dim3(Ss / 128, Bb * Hh), 128>>>(gQ, gK, gV, mask, gAO);

    // O projection (single instance)
    dim3 go(MROWS / 128, 512 / 128, 1);
    gemm_tc_kernel<<<go, 256>>>(gAO, gAO, gAO, Wo, Wo, Wo, bo, bo, bo, gP, gP, gP);

    ln_kernel<<<MROWS, 128>>>(q, gamma, beta, out);
}

// round 14
// speedup vs baseline: 1.2165x; 1.0216x over previous
#include <cuda_runtime.h>
#include <cstddef>
#include <cstdint>

#define Bb   4
#define Ss   2048
#define DIN  512
#define Hh   8
#define DM   512
#define MROWS (Bb*Ss)          // 8192

// Scratch (device globals: allocation-free rule)
__device__ float g_Q [MROWS*DM];
__device__ float g_K [MROWS*DM];
__device__ float g_V [MROWS*DM];
__device__ float g_AO[MROWS*DM];
__device__ float g_P [MROWS*DIN];

// ===========================================================================
// helpers
// ===========================================================================
__device__ __forceinline__ uint32_t f2tf32(float f) {
    uint32_t r;
    asm("cvt.rna.tf32.f32 %0, %1;" : "=r"(r) : "f"(f));
    return r;
}

// D += A * B  (m16n8k8, tf32 inputs, fp32 accum). row.col.
__device__ __forceinline__ void mma_tf32(float* d, const uint32_t* a,
                                         uint32_t b0, uint32_t b1) {
    asm volatile(
        "mma.sync.aligned.m16n8k8.row.col.f32.tf32.tf32.f32 "
        "{%0,%1,%2,%3}, {%4,%5,%6,%7}, {%8,%9}, {%0,%1,%2,%3};"
        : "+f"(d[0]), "+f"(d[1]), "+f"(d[2]), "+f"(d[3])
        : "r"(a[0]), "r"(a[1]), "r"(a[2]), "r"(a[3]), "r"(b0), "r"(b1));
}

__device__ __forceinline__ void ldsm_x4(uint32_t* r, uint32_t addr) {
    asm volatile("ldmatrix.sync.aligned.m8n8.x4.shared.b16 {%0,%1,%2,%3}, [%4];"
                 : "=r"(r[0]), "=r"(r[1]), "=r"(r[2]), "=r"(r[3]) : "r"(addr));
}

__device__ __forceinline__ void cp_async16(uint32_t dst, const void* src) {
    asm volatile("cp.async.cg.shared.global [%0], [%1], 16;"
                 :: "r"(dst), "l"(src) : "memory");
}
#define CP_COMMIT() asm volatile("cp.async.commit_group;" ::: "memory")
#define CP_WAIT0()  asm volatile("cp.async.wait_group 0;" ::: "memory")

// ===========================================================================
// Tensor-core GEMM (proven R13 body). gridDim.z selects one of up to
// 3 independent (X, W, bias, C) problem instances -> QKV in ONE launch.
// ===========================================================================
#define XS_STR 36
#define WS_STR 136

__global__ __launch_bounds__(256)
void gemm_tc_kernel(const float* __restrict__ X0, const float* __restrict__ X1,
                    const float* __restrict__ X2,
                    const float* __restrict__ W0, const float* __restrict__ W1,
                    const float* __restrict__ W2,
                    const float* __restrict__ b0p, const float* __restrict__ b1p,
                    const float* __restrict__ b2p,
                    float* __restrict__ C0, float* __restrict__ C1,
                    float* __restrict__ C2) {
    __shared__ float Xs[128 * XS_STR];
    __shared__ float Ws[32 * WS_STR];

    const int z = blockIdx.z;
    const float* X    = (z == 0) ? X0 : (z == 1) ? X1 : X2;
    const float* W    = (z == 0) ? W0 : (z == 1) ? W1 : W2;
    const float* bias = (z == 0) ? b0p : (z == 1) ? b1p : b2p;
    float*       C    = (z == 0) ? C0 : (z == 1) ? C1 : C2;

    const int tid  = threadIdx.x;
    const int lane = tid & 31;
    const int wid  = tid >> 5;
    const int gid  = lane >> 2;
    const int tig  = lane & 3;

    const int warp_m = wid >> 2;
    const int warp_n = wid & 3;
    const int m_base = warp_m * 64;
    const int n_base = warp_n * 32;

    const int bm = blockIdx.x * 128;
    const int bn = blockIdx.y * 128;

    float acc[4][4][4];
    #pragma unroll
    for (int mf = 0; mf < 4; mf++)
        #pragma unroll
        for (int nf = 0; nf < 4; nf++)
            #pragma unroll
            for (int c = 0; c < 4; c++) acc[mf][nf][c] = 0.f;

    for (int k0 = 0; k0 < 512; k0 += 32) {
        #pragma unroll
        for (int l = 0; l < 4; l++) {
            int e = tid + l * 256;
            int r = e >> 3, c4 = e & 7;
            float4 v = *(const float4*)(X + (size_t)(bm + r) * 512 + k0 + c4 * 4);
            uint4 t = { f2tf32(v.x), f2tf32(v.y), f2tf32(v.z), f2tf32(v.w) };
            *(uint4*)(Xs + r * XS_STR + c4 * 4) = t;
        }
        #pragma unroll
        for (int l = 0; l < 4; l++) {
            int e = tid + l * 256;
            int r = e >> 5, c4 = e & 31;
            float4 v = *(const float4*)(W + (size_t)(k0 + r) * 512 + bn + c4 * 4);
            uint4 t = { f2tf32(v.x), f2tf32(v.y), f2tf32(v.z), f2tf32(v.w) };
            *(uint4*)(Ws + r * WS_STR + c4 * 4) = t;
        }
        __syncthreads();

        #pragma unroll
        for (int ks = 0; ks < 4; ks++) {
            const int kk = ks * 8;
            uint32_t A[4][4];
            #pragma unroll
            for (int mf = 0; mf < 4; mf++) {
                const float* ap = Xs + (m_base + mf * 16 + gid) * XS_STR + kk + tig;
                A[mf][0] = __float_as_uint(ap[0]);
                A[mf][1] = __float_as_uint(ap[8 * XS_STR]);
                A[mf][2] = __float_as_uint(ap[4]);
                A[mf][3] = __float_as_uint(ap[8 * XS_STR + 4]);
            }
            #pragma unroll
            for (int nf = 0; nf < 4; nf++) {
                const float* bp = Ws + (kk + tig) * WS_STR + n_base + nf * 8 + gid;
                uint32_t bb0 = __float_as_uint(bp[0]);
                uint32_t bb1 = __float_as_uint(bp[4 * WS_STR]);
                #pragma unroll
                for (int mf = 0; mf < 4; mf++)
                    mma_tf32(acc[mf][nf], A[mf], bb0, bb1);
            }
        }
        __syncthreads();
    }

    #pragma unroll
    for (int nf = 0; nf < 4; nf++) {
        const int col = bn + n_base + nf * 8 + 2 * tig;
        float2 b2 = *(const float2*)(bias + col);
        #pragma unroll
        for (int mf = 0; mf < 4; mf++) {
            const int row0 = bm + m_base + mf * 16 + gid;
            float2 o0 = { acc[mf][nf][0] + b2.x, acc[mf][nf][1] + b2.y };
            float2 o1 = { acc[mf][nf][2] + b2.x, acc[mf][nf][3] + b2.y };
            *(float2*)(C + (size_t)row0 * 512 + col) = o0;
            *(float2*)(C + (size_t)(row0 + 8) * 512 + col) = o1;
        }
    }
}

// ===========================================================================
// mma.sync tf32 flash attention, v6: R13/v4 structure with cp.async K/V
// loads (LDGSTS, reg-free) issued at loop top for max overlap. K/V enter
// the MMA as truncated tf32 (RZ) instead of RNA-rounded.
// ===========================================================================
#define KSTR 68
#define VSTR 72
#define SM_K0 0
#define SM_K1 (32*KSTR)
#define SM_V0 (2*32*KSTR)
#define SM_V1 (SM_V0 + 32*VSTR)
#define ATTN_SMEM_FLOATS (SM_V0 + 2*32*VSTR)   // 8960 floats = 35840 B

__global__ __launch_bounds__(128, 2)
void attn_mma_kernel(const float* __restrict__ Qg, const float* __restrict__ Kg,
                     const float* __restrict__ Vg, const float* __restrict__ mask,
                     float* __restrict__ AO) {
    __shared__ float sm[ATTN_SMEM_FLOATS];
    const int tid  = threadIdx.x;
    const int lane = tid & 31;
    const int wid  = tid >> 5;        // 0..3
    const int gid  = lane >> 2;
    const int tig  = lane & 3;
    const int srcA = (lane & ~3) | (tig >> 1);
    const int srcB = srcA + 2;
    const bool odd = (tig & 1);

    const int lm_base = (lane & 7) * KSTR + ((lane >> 3) & 1) * 4 + (lane >> 4) * 8;
    const uint32_t sm_u   = (uint32_t)__cvta_generic_to_shared(sm);
    const uint32_t smK0_u = sm_u + 4u * SM_K0;
    const uint32_t smK1_u = sm_u + 4u * SM_K1;
    const uint32_t smV0_u = sm_u + 4u * SM_V0;
    const uint32_t smV1_u = sm_u + 4u * SM_V1;

    const int bh = blockIdx.y;
    const int b  = bh >> 3;
    const int h  = bh & 7;
    const int q0 = blockIdx.x * 128;

    const float* Kb = Kg + (size_t)b * Ss * 512 + h * 64;
    const float* Vb = Vg + (size_t)b * Ss * 512 + h * 64;

    // per-thread cp.async coordinates (4 rows x 1 float4 each, x4 iters)
    const int cr = tid >> 4;          // 0..7  (row base, +8 per iter)
    const int cc = (tid & 15) * 4;    // float4 column

    auto load_kv_async = [&](int k0, int sel) {
        const uint32_t Ks = sel ? smK1_u : smK0_u;
        const uint32_t Vs = sel ? smV1_u : smV0_u;
        #pragma unroll
        for (int l = 0; l < 4; l++) {
            int r = cr + l * 8;
            const float* kp = Kb + (size_t)(k0 + r) * 512 + cc;
            const float* vp = Vb + (size_t)(k0 + r) * 512 + cc;
            cp_async16(Ks + 4u * (r * KSTR + cc), kp);
            cp_async16(Vs + 4u * (r * VSTR + cc), vp);
        }
        CP_COMMIT();
    };

    load_kv_async(0, 0);

    // persistent Q A-fragments (pre-scaled 1/8, tf32 RNA)
    const int qrow0 = q0 + wid * 32 + gid;
    const int qrow1 = qrow0 + 16;
    uint32_t Qa[2][8][4];
    #pragma unroll
    for (int mf = 0; mf < 2; mf++) {
        const float* Qp = Qg + ((size_t)b * Ss + (mf ? qrow1 : qrow0)) * 512 + h * 64;
        #pragma unroll
        for (int ch = 0; ch < 8; ch++) {
            Qa[mf][ch][0] = f2tf32(Qp[ch * 8 + tig] * 0.125f);
            Qa[mf][ch][1] = f2tf32(Qp[8 * 512 + ch * 8 + tig] * 0.125f);
            Qa[mf][ch][2] = f2tf32(Qp[ch * 8 + tig + 4] * 0.125f);
            Qa[mf][ch][3] = f2tf32(Qp[8 * 512 + ch * 8 + tig + 4] * 0.125f);
        }
    }

    const float* Mr[4];
    Mr[0] = mask + (size_t)b * Ss * Ss + (size_t)qrow0 * Ss;
    Mr[1] = Mr[0] + (size_t)8 * Ss;
    Mr[2] = mask + (size_t)b * Ss * Ss + (size_t)qrow1 * Ss;
    Mr[3] = Mr[2] + (size_t)8 * Ss;

    float mI[4] = {-1e30f, -1e30f, -1e30f, -1e30f};
    float lI[4] = {0.f, 0.f, 0.f, 0.f};
    float O[2][8][4];
    #pragma unroll
    for (int mf = 0; mf < 2; mf++)
        #pragma unroll
        for (int j = 0; j < 8; j++)
            #pragma unroll
            for (int c = 0; c < 4; c++) O[mf][j][c] = 0.f;

    for (int kt = 0; kt < 64; kt++) {
        const int sel = kt & 1;
        const int k0  = kt * 32;
        const float* Vs = sm + (sel ? SM_V1 : SM_V0);
        const uint32_t smK_u = sel ? smK1_u : smK0_u;

        // current tile's copies complete + visible CTA-wide
        CP_WAIT0();
        __syncthreads();

        // fire next tile immediately: copy overlaps ALL compute below
        if (kt < 63) load_kv_async(k0 + 32, sel ^ 1);

        float2 mk[4][4];
        #pragma unroll
        for (int r = 0; r < 4; r++)
            #pragma unroll
            for (int kf = 0; kf < 4; kf++)
                mk[r][kf] = *(const float2*)(Mr[r] + k0 + kf * 8 + 2 * tig);

        float S[2][4][4];
        #pragma unroll
        for (int mf = 0; mf < 2; mf++)
            #pragma unroll
            for (int kf = 0; kf < 4; kf++)
                #pragma unroll
                for (int c = 0; c < 4; c++) S[mf][kf][c] = 0.f;

        #pragma unroll
        for (int kf = 0; kf < 4; kf++) {
            #pragma unroll
            for (int ch2 = 0; ch2 < 4; ch2++) {
                uint32_t r[4];
                ldsm_x4(r, smK_u + 4u * (uint32_t)(kf * 8 * KSTR + ch2 * 16 + lm_base));
                mma_tf32(S[0][kf], Qa[0][2 * ch2],     r[0], r[1]);
                mma_tf32(S[0][kf], Qa[0][2 * ch2 + 1], r[2], r[3]);
                mma_tf32(S[1][kf], Qa[1][2 * ch2],     r[0], r[1]);
                mma_tf32(S[1][kf], Qa[1][2 * ch2 + 1], r[2], r[3]);
            }
        }

        #pragma unroll
        for (int mf = 0; mf < 2; mf++) {
            const int rA = mf * 2, rB = mf * 2 + 1;
            float mx0 = mI[rA], mx1 = mI[rB];
            #pragma unroll
            for (int kf = 0; kf < 4; kf++) {
                float s0 = S[mf][kf][0] * mk[rA][kf].x;
                float s1 = S[mf][kf][1] * mk[rA][kf].y;
                float s2 = S[mf][kf][2] * mk[rB][kf].x;
                float s3 = S[mf][kf][3] * mk[rB][kf].y;
                s0 = (s0 > 0.f) ? s0 : -10000.f;
                s1 = (s1 > 0.f) ? s1 : -10000.f;
                s2 = (s2 > 0.f) ? s2 : -10000.f;
                s3 = (s3 > 0.f) ? s3 : -10000.f;
                S[mf][kf][0] = s0; S[mf][kf][1] = s1;
                S[mf][kf][2] = s2; S[mf][kf][3] = s3;
                mx0 = fmaxf(mx0, fmaxf(s0, s1));
                mx1 = fmaxf(mx1, fmaxf(s2, s3));
            }
            mx0 = fmaxf(mx0, __shfl_xor_sync(0xffffffffu, mx0, 1));
            mx0 = fmaxf(mx0, __shfl_xor_sync(0xffffffffu, mx0, 2));
            mx1 = fmaxf(mx1, __shfl_xor_sync(0xffffffffu, mx1, 1));
            mx1 = fmaxf(mx1, __shfl_xor_sync(0xffffffffu, mx1, 2));

            float f0 = __expf(mI[rA] - mx0);
            float f1 = __expf(mI[rB] - mx1);
            float sum0 = 0.f, sum1 = 0.f;
            #pragma unroll
            for (int kf = 0; kf < 4; kf++) {
                float p0 = __expf(S[mf][kf][0] - mx0);
                float p1 = __expf(S[mf][kf][1] - mx0);
                float p2 = __expf(S[mf][kf][2] - mx1);
                float p3 = __expf(S[mf][kf][3] - mx1);
                sum0 += p0 + p1;
                sum1 += p2 + p3;
                S[mf][kf][0] = __uint_as_float(f2tf32(p0));
                S[mf][kf][1] = __uint_as_float(f2tf32(p1));
                S[mf][kf][2] = __uint_as_float(f2tf32(p2));
                S[mf][kf][3] = __uint_as_float(f2tf32(p3));
            }
            sum0 += __shfl_xor_sync(0xffffffffu, sum0, 1);
            sum0 += __shfl_xor_sync(0xffffffffu, sum0, 2);
            sum1 += __shfl_xor_sync(0xffffffffu, sum1, 1);
            sum1 += __shfl_xor_sync(0xffffffffu, sum1, 2);

            lI[rA] = lI[rA] * f0 + sum0;  mI[rA] = mx0;
            lI[rB] = lI[rB] * f1 + sum1;  mI[rB] = mx1;

            #pragma unroll
            for (int j = 0; j < 8; j++) {
                O[mf][j][0] *= f0; O[mf][j][1] *= f0;
                O[mf][j][2] *= f1; O[mf][j][3] *= f1;
            }
        }

        #pragma unroll
        for (int kc = 0; kc < 4; kc++) {
            uint32_t A[2][4];
            #pragma unroll
            for (int mf = 0; mf < 2; mf++) {
                float x0 = __shfl_sync(0xffffffffu, S[mf][kc][0], srcA);
                float x1 = __shfl_sync(0xffffffffu, S[mf][kc][1], srcA);
                float y0 = __shfl_sync(0xffffffffu, S[mf][kc][2], srcA);
                float y1 = __shfl_sync(0xffffffffu, S[mf][kc][3], srcA);
                float z0 = __shfl_sync(0xffffffffu, S[mf][kc][0], srcB);
                float z1 = __shfl_sync(0xffffffffu, S[mf][kc][1], srcB);
                float w0 = __shfl_sync(0xffffffffu, S[mf][kc][2], srcB);
                float w1 = __shfl_sync(0xffffffffu, S[mf][kc][3], srcB);
                A[mf][0] = __float_as_uint(odd ? x1 : x0);
                A[mf][1] = __float_as_uint(odd ? y1 : y0);
                A[mf][2] = __float_as_uint(odd ? z1 : z0);
                A[mf][3] = __float_as_uint(odd ? w1 : w0);
            }
            #pragma unroll
            for (int df = 0; df < 8; df++) {
                const float* vp = Vs + (kc * 8 + tig) * VSTR + df * 8 + gid;
                uint32_t b0 = __float_as_uint(vp[0]);
                uint32_t b1 = __float_as_uint(vp[4 * VSTR]);
                mma_tf32(O[0][df], A[0], b0, b1);
                mma_tf32(O[1][df], A[1], b0, b1);
            }
        }
    }

    #pragma unroll
    for (int mf = 0; mf < 2; mf++) {
        const int rA = mf * 2, rB = mf * 2 + 1;
        const float inv0 = 1.f / lI[rA];
        const float inv1 = 1.f / lI[rB];
        float* Op0 = AO + ((size_t)b * Ss + (mf ? qrow1 : qrow0)) * 512 + h * 64;
        float* Op1 = Op0 + (size_t)8 * 512;
        #pragma unroll
        for (int df = 0; df < 8; df++) {
            float2 o0 = { O[mf][df][0] * inv0, O[mf][df][1] * inv0 };
            float2 o1 = { O[mf][df][2] * inv1, O[mf][df][3] * inv1 };
            *(float2*)(Op0 + df * 8 + 2 * tig) = o0;
            *(float2*)(Op1 + df * 8 + 2 * tig) = o1;
        }
    }
}

// ===========================================================================
// Residual + LayerNorm: 128 threads x float4 per 512-wide row (proven R10).
// ===========================================================================
__global__ __launch_bounds__(128)
void ln_kernel(const float* __restrict__ q, const float* __restrict__ gamma,
               const float* __restrict__ beta, float* __restrict__ out) {
    __shared__ float rs[4], rs2[4];
    const int r = blockIdx.x;
    const int j = threadIdx.x;          // 0..127
    const int w = j >> 5, ln = j & 31;

    float4 qv = *(const float4*)(q + (size_t)r * 512 + j * 4);
    float4 pv = *(const float4*)(g_P + (size_t)r * 512 + j * 4);
    float4 v  = { qv.x + pv.x, qv.y + pv.y, qv.z + pv.z, qv.w + pv.w };

    float s  = v.x + v.y + v.z + v.w;
    float s2 = v.x * v.x + v.y * v.y + v.z * v.z + v.w * v.w;
    #pragma unroll
    for (int o = 16; o > 0; o >>= 1) {
        s  += __shfl_xor_sync(0xffffffffu, s,  o);
        s2 += __shfl_xor_sync(0xffffffffu, s2, o);
    }
    if (ln == 0) { rs[w] = s; rs2[w] = s2; }
    __syncthreads();
    s  = rs[0]  + rs[1]  + rs[2]  + rs[3];
    s2 = rs2[0] + rs2[1] + rs2[2] + rs2[3];

    const float mu  = s * (1.f / 512.f);
    const float var = s2 * (1.f / 512.f) - mu * mu;
    const float inv = rsqrtf(var + 1e-5f);

    float4 g4 = *(const float4*)(gamma + j * 4);
    float4 b4 = *(const float4*)(beta + j * 4);
    float4 o;
    o.x = (v.x - mu) * inv * g4.x + b4.x;
    o.y = (v.y - mu) * inv * g4.y + b4.y;
    o.z = (v.z - mu) * inv * g4.z + b4.z;
    o.w = (v.w - mu) * inv * g4.w + b4.w;
    *(float4*)(out + (size_t)r * 512 + j * 4) = o;
}

// ===========================================================================
extern "C" void kernel_launch(void* const* d_in, const int* in_sizes, int n_in,
                              void* d_out, int out_size) {
    const float* q     = (const float*)d_in[0];
    const float* k     = (const float*)d_in[1];
    const float* v     = (const float*)d_in[2];
    const float* mask  = (const float*)d_in[3];
    const float* Wq    = (const float*)d_in[4];
    const float* bq    = (const float*)d_in[5];
    const float* Wk    = (const float*)d_in[6];
    const float* bk    = (const float*)d_in[7];
    const float* Wv    = (const float*)d_in[8];
    const float* bv    = (const float*)d_in[9];
    const float* Wo    = (const float*)d_in[10];
    const float* bo    = (const float*)d_in[11];
    const float* gamma = (const float*)d_in[12];
    const float* beta  = (const float*)d_in[13];
    float* out = (float*)d_out;

    float *gQ, *gK, *gV, *gAO, *gP;
    cudaGetSymbolAddress((void**)&gQ,  g_Q);
    cudaGetSymbolAddress((void**)&gK,  g_K);
    cudaGetSymbolAddress((void**)&gV,  g_V);
    cudaGetSymbolAddress((void**)&gAO, g_AO);
    cudaGetSymbolAddress((void**)&gP,  g_P);

    // QKV projections fused into one launch (z = 0,1,2)
    dim3 gqkv(MROWS / 128, 512 / 128, 3);
    gemm_tc_kernel<<<gqkv, 256>>>(q, k, v, Wq, Wk, Wv, bq, bk, bv, gQ, gK, gV);

    attn_mma_kernel<<<dim3(Ss / 128, Bb * Hh), 128>>>(gQ, gK, gV, mask, gAO);

    // O projection (single instance)
    dim3 go(MROWS / 128, 512 / 128, 1);
    gemm_tc_kernel<<<go, 256>>>(gAO, gAO, gAO, Wo, Wo, Wo, bo, bo, bo, gP, gP, gP);

    ln_kernel<<<MROWS, 128>>>(q, gamma, beta, out);
}

// round 15
// speedup vs baseline: 1.2599x; 1.0356x over previous
#include <cuda_runtime.h>
#include <cstddef>
#include <cstdint>

#define Bb   4
#define Ss   2048
#define DIN  512
#define Hh   8
#define DM   512
#define MROWS (Bb*Ss)          // 8192

// Scratch (device globals: allocation-free rule)
__device__ float g_Q [MROWS*DM];
__device__ float g_K [MROWS*DM];
__device__ float g_V [MROWS*DM];
__device__ float g_AO[MROWS*DM];
__device__ float g_P [MROWS*DIN];

// ===========================================================================
// helpers
// ===========================================================================
__device__ __forceinline__ uint32_t f2tf32(float f) {
    uint32_t r;
    asm("cvt.rna.tf32.f32 %0, %1;" : "=r"(r) : "f"(f));
    return r;
}

// D += A * B  (m16n8k8, tf32 inputs, fp32 accum). row.col.
__device__ __forceinline__ void mma_tf32(float* d, const uint32_t* a,
                                         uint32_t b0, uint32_t b1) {
    asm volatile(
        "mma.sync.aligned.m16n8k8.row.col.f32.tf32.tf32.f32 "
        "{%0,%1,%2,%3}, {%4,%5,%6,%7}, {%8,%9}, {%0,%1,%2,%3};"
        : "+f"(d[0]), "+f"(d[1]), "+f"(d[2]), "+f"(d[3])
        : "r"(a[0]), "r"(a[1]), "r"(a[2]), "r"(a[3]), "r"(b0), "r"(b1));
}

__device__ __forceinline__ void ldsm_x4(uint32_t* r, uint32_t addr) {
    asm volatile("ldmatrix.sync.aligned.m8n8.x4.shared.b16 {%0,%1,%2,%3}, [%4];"
                 : "=r"(r[0]), "=r"(r[1]), "=r"(r[2]), "=r"(r[3]) : "r"(addr));
}

__device__ __forceinline__ void cp_async16(uint32_t dst, const void* src) {
    asm volatile("cp.async.cg.shared.global [%0], [%1], 16;"
                 :: "r"(dst), "l"(src) : "memory");
}
#define CP_COMMIT() asm volatile("cp.async.commit_group;" ::: "memory")
#define CP_WAIT0()  asm volatile("cp.async.wait_group 0;" ::: "memory")
#define CP_WAIT1()  asm volatile("cp.async.wait_group 1;" ::: "memory")

// ===========================================================================
// Tensor-core GEMM, cp.async double-buffered, ONE barrier per k-step.
// BM=128, BN=128, BK=32, 256 threads. gridDim.z selects up to 3 instances.
// X/W enter MMA RZ-truncated (cp.async skips the cvt).
// ===========================================================================
#define XS_STR 36
#define WS_STR 136
#define GEMM_STAGE_FLOATS (128*XS_STR + 32*WS_STR)      // 8960
#define GEMM_SMEM_BYTES (2 * GEMM_STAGE_FLOATS * 4)     // 71680

__global__ __launch_bounds__(256)
void gemm_tc_kernel(const float* __restrict__ X0, const float* __restrict__ X1,
                    const float* __restrict__ X2,
                    const float* __restrict__ W0, const float* __restrict__ W1,
                    const float* __restrict__ W2,
                    const float* __restrict__ b0p, const float* __restrict__ b1p,
                    const float* __restrict__ b2p,
                    float* __restrict__ C0, float* __restrict__ C1,
                    float* __restrict__ C2) {
    extern __shared__ float gsm[];

    const int z = blockIdx.z;
    const float* X    = (z == 0) ? X0 : (z == 1) ? X1 : X2;
    const float* W    = (z == 0) ? W0 : (z == 1) ? W1 : W2;
    const float* bias = (z == 0) ? b0p : (z == 1) ? b1p : b2p;
    float*       C    = (z == 0) ? C0 : (z == 1) ? C1 : C2;

    const int tid  = threadIdx.x;
    const int lane = tid & 31;
    const int wid  = tid >> 5;
    const int gid  = lane >> 2;
    const int tig  = lane & 3;

    const int warp_m = wid >> 2;
    const int warp_n = wid & 3;
    const int m_base = warp_m * 64;
    const int n_base = warp_n * 32;

    const int bm = blockIdx.x * 128;
    const int bn = blockIdx.y * 128;

    const uint32_t gsm_u = (uint32_t)__cvta_generic_to_shared(gsm);

    // cp.async coordinates (full-tile: X 4 float4/thr, W 4 float4/thr)
    auto issue_stage = [&](int k0, int s) {
        const uint32_t Xs_u = gsm_u + 4u * (s * GEMM_STAGE_FLOATS);
        const uint32_t Ws_u = Xs_u + 4u * (128 * XS_STR);
        #pragma unroll
        for (int l = 0; l < 4; l++) {
            int e = tid + l * 256;
            int r = e >> 3, c4 = e & 7;
            cp_async16(Xs_u + 4u * (r * XS_STR + c4 * 4),
                       X + (size_t)(bm + r) * 512 + k0 + c4 * 4);
        }
        #pragma unroll
        for (int l = 0; l < 4; l++) {
            int e = tid + l * 256;
            int r = e >> 5, c4 = e & 31;
            cp_async16(Ws_u + 4u * (r * WS_STR + c4 * 4),
                       W + (size_t)(k0 + r) * 512 + bn + c4 * 4);
        }
        CP_COMMIT();
    };

    float acc[4][4][4];
    #pragma unroll
    for (int mf = 0; mf < 4; mf++)
        #pragma unroll
        for (int nf = 0; nf < 4; nf++)
            #pragma unroll
            for (int c = 0; c < 4; c++) acc[mf][nf][c] = 0.f;

    issue_stage(0, 0);

    for (int it = 0; it < 16; it++) {
        const int buf = it & 1;
        const float* Xs = gsm + buf * GEMM_STAGE_FLOATS;
        const float* Ws = Xs + 128 * XS_STR;

        CP_WAIT0();
        __syncthreads();
        if (it < 15) issue_stage((it + 1) * 32, buf ^ 1);

        #pragma unroll
        for (int ks = 0; ks < 4; ks++) {
            const int kk = ks * 8;
            uint32_t A[4][4];
            #pragma unroll
            for (int mf = 0; mf < 4; mf++) {
                const float* ap = Xs + (m_base + mf * 16 + gid) * XS_STR + kk + tig;
                A[mf][0] = __float_as_uint(ap[0]);
                A[mf][1] = __float_as_uint(ap[8 * XS_STR]);
                A[mf][2] = __float_as_uint(ap[4]);
                A[mf][3] = __float_as_uint(ap[8 * XS_STR + 4]);
            }
            #pragma unroll
            for (int nf = 0; nf < 4; nf++) {
                const float* bp = Ws + (kk + tig) * WS_STR + n_base + nf * 8 + gid;
                uint32_t bb0 = __float_as_uint(bp[0]);
                uint32_t bb1 = __float_as_uint(bp[4 * WS_STR]);
                #pragma unroll
                for (int mf = 0; mf < 4; mf++)
                    mma_tf32(acc[mf][nf], A[mf], bb0, bb1);
            }
        }
    }

    #pragma unroll
    for (int nf = 0; nf < 4; nf++) {
        const int col = bn + n_base + nf * 8 + 2 * tig;
        float2 b2 = *(const float2*)(bias + col);
        #pragma unroll
        for (int mf = 0; mf < 4; mf++) {
            const int row0 = bm + m_base + mf * 16 + gid;
            float2 o0 = { acc[mf][nf][0] + b2.x, acc[mf][nf][1] + b2.y };
            float2 o1 = { acc[mf][nf][2] + b2.x, acc[mf][nf][3] + b2.y };
            *(float2*)(C + (size_t)row0 * 512 + col) = o0;
            *(float2*)(C + (size_t)(row0 + 8) * 512 + col) = o1;
        }
    }
}

// ===========================================================================
// mma.sync tf32 flash attention, v7: R14/v6 with 3-stage cp.async pipeline
// (wait_group 1 -> copies span two compute bodies).
// ===========================================================================
#define KSTR 68
#define VSTR 72
#define ATTN_STAGE_FLOATS (32*KSTR + 32*VSTR)            // 4480
#define ATTN_SMEM_BYTES (3 * ATTN_STAGE_FLOATS * 4)      // 53760

__global__ __launch_bounds__(128, 2)
void attn_mma_kernel(const float* __restrict__ Qg, const float* __restrict__ Kg,
                     const float* __restrict__ Vg, const float* __restrict__ mask,
                     float* __restrict__ AO) {
    extern __shared__ float sm[];
    const int tid  = threadIdx.x;
    const int lane = tid & 31;
    const int wid  = tid >> 5;        // 0..3
    const int gid  = lane >> 2;
    const int tig  = lane & 3;
    const int srcA = (lane & ~3) | (tig >> 1);
    const int srcB = srcA + 2;
    const bool odd = (tig & 1);

    const int lm_base = (lane & 7) * KSTR + ((lane >> 3) & 1) * 4 + (lane >> 4) * 8;
    const uint32_t sm_u = (uint32_t)__cvta_generic_to_shared(sm);

    const int bh = blockIdx.y;
    const int b  = bh >> 3;
    const int h  = bh & 7;
    const int q0 = blockIdx.x * 128;

    const float* Kb = Kg + (size_t)b * Ss * 512 + h * 64;
    const float* Vb = Vg + (size_t)b * Ss * 512 + h * 64;

    // per-thread cp.async coordinates
    const int cr = tid >> 4;          // 0..7
    const int cc = (tid & 15) * 4;    // float4 column

    auto load_kv_async = [&](int k0, int stage) {
        const uint32_t Ks = sm_u + 4u * (stage * ATTN_STAGE_FLOATS);
        const uint32_t Vs = Ks + 4u * (32 * KSTR);
        #pragma unroll
        for (int l = 0; l < 4; l++) {
            int r = cr + l * 8;
            cp_async16(Ks + 4u * (r * KSTR + cc), Kb + (size_t)(k0 + r) * 512 + cc);
            cp_async16(Vs + 4u * (r * VSTR + cc), Vb + (size_t)(k0 + r) * 512 + cc);
        }
        CP_COMMIT();
    };

    load_kv_async(0, 0);
    load_kv_async(32, 1);

    // persistent Q A-fragments (pre-scaled 1/8, tf32 RNA)
    const int qrow0 = q0 + wid * 32 + gid;
    const int qrow1 = qrow0 + 16;
    uint32_t Qa[2][8][4];
    #pragma unroll
    for (int mf = 0; mf < 2; mf++) {
        const float* Qp = Qg + ((size_t)b * Ss + (mf ? qrow1 : qrow0)) * 512 + h * 64;
        #pragma unroll
        for (int ch = 0; ch < 8; ch++) {
            Qa[mf][ch][0] = f2tf32(Qp[ch * 8 + tig] * 0.125f);
            Qa[mf][ch][1] = f2tf32(Qp[8 * 512 + ch * 8 + tig] * 0.125f);
            Qa[mf][ch][2] = f2tf32(Qp[ch * 8 + tig + 4] * 0.125f);
            Qa[mf][ch][3] = f2tf32(Qp[8 * 512 + ch * 8 + tig + 4] * 0.125f);
        }
    }

    const float* Mr[4];
    Mr[0] = mask + (size_t)b * Ss * Ss + (size_t)qrow0 * Ss;
    Mr[1] = Mr[0] + (size_t)8 * Ss;
    Mr[2] = mask + (size_t)b * Ss * Ss + (size_t)qrow1 * Ss;
    Mr[3] = Mr[2] + (size_t)8 * Ss;

    float mI[4] = {-1e30f, -1e30f, -1e30f, -1e30f};
    float lI[4] = {0.f, 0.f, 0.f, 0.f};
    float O[2][8][4];
    #pragma unroll
    for (int mf = 0; mf < 2; mf++)
        #pragma unroll
        for (int j = 0; j < 8; j++)
            #pragma unroll
            for (int c = 0; c < 4; c++) O[mf][j][c] = 0.f;

    int stage = 0;
    for (int kt = 0; kt < 64; kt++) {
        const int k0 = kt * 32;
        const uint32_t smK_u = sm_u + 4u * (stage * ATTN_STAGE_FLOATS);
        const float* Vs = sm + stage * ATTN_STAGE_FLOATS + 32 * KSTR;

        // tile kt's copy complete (kt+1 may still be in flight)
        CP_WAIT1();
        __syncthreads();

        // fire tile kt+2 into the stage last read at kt-1
        if (kt < 62) load_kv_async(k0 + 64, (stage + 2) % 3);

        float2 mk[4][4];
        #pragma unroll
        for (int r = 0; r < 4; r++)
            #pragma unroll
            for (int kf = 0; kf < 4; kf++)
                mk[r][kf] = *(const float2*)(Mr[r] + k0 + kf * 8 + 2 * tig);

        float S[2][4][4];
        #pragma unroll
        for (int mf = 0; mf < 2; mf++)
            #pragma unroll
            for (int kf = 0; kf < 4; kf++)
                #pragma unroll
                for (int c = 0; c < 4; c++) S[mf][kf][c] = 0.f;

        #pragma unroll
        for (int kf = 0; kf < 4; kf++) {
            #pragma unroll
            for (int ch2 = 0; ch2 < 4; ch2++) {
                uint32_t r[4];
                ldsm_x4(r, smK_u + 4u * (uint32_t)(kf * 8 * KSTR + ch2 * 16 + lm_base));
                mma_tf32(S[0][kf], Qa[0][2 * ch2],     r[0], r[1]);
                mma_tf32(S[0][kf], Qa[0][2 * ch2 + 1], r[2], r[3]);
                mma_tf32(S[1][kf], Qa[1][2 * ch2],     r[0], r[1]);
                mma_tf32(S[1][kf], Qa[1][2 * ch2 + 1], r[2], r[3]);
            }
        }

        #pragma unroll
        for (int mf = 0; mf < 2; mf++) {
            const int rA = mf * 2, rB = mf * 2 + 1;
            float mx0 = mI[rA], mx1 = mI[rB];
            #pragma unroll
            for (int kf = 0; kf < 4; kf++) {
                float s0 = S[mf][kf][0] * mk[rA][kf].x;
                float s1 = S[mf][kf][1] * mk[rA][kf].y;
                float s2 = S[mf][kf][2] * mk[rB][kf].x;
                float s3 = S[mf][kf][3] * mk[rB][kf].y;
                s0 = (s0 > 0.f) ? s0 : -10000.f;
                s1 = (s1 > 0.f) ? s1 : -10000.f;
                s2 = (s2 > 0.f) ? s2 : -10000.f;
                s3 = (s3 > 0.f) ? s3 : -10000.f;
                S[mf][kf][0] = s0; S[mf][kf][1] = s1;
                S[mf][kf][2] = s2; S[mf][kf][3] = s3;
                mx0 = fmaxf(mx0, fmaxf(s0, s1));
                mx1 = fmaxf(mx1, fmaxf(s2, s3));
            }
            mx0 = fmaxf(mx0, __shfl_xor_sync(0xffffffffu, mx0, 1));
            mx0 = fmaxf(mx0, __shfl_xor_sync(0xffffffffu, mx0, 2));
            mx1 = fmaxf(mx1, __shfl_xor_sync(0xffffffffu, mx1, 1));
            mx1 = fmaxf(mx1, __shfl_xor_sync(0xffffffffu, mx1, 2));

            float f0 = __expf(mI[rA] - mx0);
            float f1 = __expf(mI[rB] - mx1);
            float sum0 = 0.f, sum1 = 0.f;
            #pragma unroll
            for (int kf = 0; kf < 4; kf++) {
                float p0 = __expf(S[mf][kf][0] - mx0);
                float p1 = __expf(S[mf][kf][1] - mx0);
                float p2 = __expf(S[mf][kf][2] - mx1);
                float p3 = __expf(S[mf][kf][3] - mx1);
                sum0 += p0 + p1;
                sum1 += p2 + p3;
                S[mf][kf][0] = __uint_as_float(f2tf32(p0));
                S[mf][kf][1] = __uint_as_float(f2tf32(p1));
                S[mf][kf][2] = __uint_as_float(f2tf32(p2));
                S[mf][kf][3] = __uint_as_float(f2tf32(p3));
            }
            sum0 += __shfl_xor_sync(0xffffffffu, sum0, 1);
            sum0 += __shfl_xor_sync(0xffffffffu, sum0, 2);
            sum1 += __shfl_xor_sync(0xffffffffu, sum1, 1);
            sum1 += __shfl_xor_sync(0xffffffffu, sum1, 2);

            lI[rA] = lI[rA] * f0 + sum0;  mI[rA] = mx0;
            lI[rB] = lI[rB] * f1 + sum1;  mI[rB] = mx1;

            #pragma unroll
            for (int j = 0; j < 8; j++) {
                O[mf][j][0] *= f0; O[mf][j][1] *= f0;
                O[mf][j][2] *= f1; O[mf][j][3] *= f1;
            }
        }

        #pragma unroll
        for (int kc = 0; kc < 4; kc++) {
            uint32_t A[2][4];
            #pragma unroll
            for (int mf = 0; mf < 2; mf++) {
                float x0 = __shfl_sync(0xffffffffu, S[mf][kc][0], srcA);
                float x1 = __shfl_sync(0xffffffffu, S[mf][kc][1], srcA);
                float y0 = __shfl_sync(0xffffffffu, S[mf][kc][2], srcA);
                float y1 = __shfl_sync(0xffffffffu, S[mf][kc][3], srcA);
                float z0 = __shfl_sync(0xffffffffu, S[mf][kc][0], srcB);
                float z1 = __shfl_sync(0xffffffffu, S[mf][kc][1], srcB);
                float w0 = __shfl_sync(0xffffffffu, S[mf][kc][2], srcB);
                float w1 = __shfl_sync(0xffffffffu, S[mf][kc][3], srcB);
                A[mf][0] = __float_as_uint(odd ? x1 : x0);
                A[mf][1] = __float_as_uint(odd ? y1 : y0);
                A[mf][2] = __float_as_uint(odd ? z1 : z0);
                A[mf][3] = __float_as_uint(odd ? w1 : w0);
            }
            #pragma unroll
            for (int df = 0; df < 8; df++) {
                const float* vp = Vs + (kc * 8 + tig) * VSTR + df * 8 + gid;
                uint32_t b0 = __float_as_uint(vp[0]);
                uint32_t b1 = __float_as_uint(vp[4 * VSTR]);
                mma_tf32(O[0][df], A[0], b0, b1);
                mma_tf32(O[1][df], A[1], b0, b1);
            }
        }

        stage = (stage + 1) % 3;
    }

    #pragma unroll
    for (int mf = 0; mf < 2; mf++) {
        const int rA = mf * 2, rB = mf * 2 + 1;
        const float inv0 = 1.f / lI[rA];
        const float inv1 = 1.f / lI[rB];
        float* Op0 = AO + ((size_t)b * Ss + (mf ? qrow1 : qrow0)) * 512 + h * 64;
        float* Op1 = Op0 + (size_t)8 * 512;
        #pragma unroll
        for (int df = 0; df < 8; df++) {
            float2 o0 = { O[mf][df][0] * inv0, O[mf][df][1] * inv0 };
            float2 o1 = { O[mf][df][2] * inv1, O[mf][df][3] * inv1 };
            *(float2*)(Op0 + df * 8 + 2 * tig) = o0;
            *(float2*)(Op1 + df * 8 + 2 * tig) = o1;
        }
    }
}

// ===========================================================================
// Residual + LayerNorm: 128 threads x float4 per 512-wide row (proven R10).
// ===========================================================================
__global__ __launch_bounds__(128)
void ln_kernel(const float* __restrict__ q, const float* __restrict__ gamma,
               const float* __restrict__ beta, float* __restrict__ out) {
    __shared__ float rs[4], rs2[4];
    const int r = blockIdx.x;
    const int j = threadIdx.x;          // 0..127
    const int w = j >> 5, ln = j & 31;

    float4 qv = *(const float4*)(q + (size_t)r * 512 + j * 4);
    float4 pv = *(const float4*)(g_P + (size_t)r * 512 + j * 4);
    float4 v  = { qv.x + pv.x, qv.y + pv.y, qv.z + pv.z, qv.w + pv.w };

    float s  = v.x + v.y + v.z + v.w;
    float s2 = v.x * v.x + v.y * v.y + v.z * v.z + v.w * v.w;
    #pragma unroll
    for (int o = 16; o > 0; o >>= 1) {
        s  += __shfl_xor_sync(0xffffffffu, s,  o);
        s2 += __shfl_xor_sync(0xffffffffu, s2, o);
    }
    if (ln == 0) { rs[w] = s; rs2[w] = s2; }
    __syncthreads();
    s  = rs[0]  + rs[1]  + rs[2]  + rs[3];
    s2 = rs2[0] + rs2[1] + rs2[2] + rs2[3];

    const float mu  = s * (1.f / 512.f);
    const float var = s2 * (1.f / 512.f) - mu * mu;
    const float inv = rsqrtf(var + 1e-5f);

    float4 g4 = *(const float4*)(gamma + j * 4);
    float4 b4 = *(const float4*)(beta + j * 4);
    float4 o;
    o.x = (v.x - mu) * inv * g4.x + b4.x;
    o.y = (v.y - mu) * inv * g4.y + b4.y;
    o.z = (v.z - mu) * inv * g4.z + b4.z;
    o.w = (v.w - mu) * inv * g4.w + b4.w;
    *(float4*)(out + (size_t)r * 512 + j * 4) = o;
}

// ===========================================================================
extern "C" void kernel_launch(void* const* d_in, const int* in_sizes, int n_in,
                              void* d_out, int out_size) {
    const float* q     = (const float*)d_in[0];
    const float* k     = (const float*)d_in[1];
    const float* v     = (const float*)d_in[2];
    const float* mask  = (const float*)d_in[3];
    const float* Wq    = (const float*)d_in[4];
    const float* bq    = (const float*)d_in[5];
    const float* Wk    = (const float*)d_in[6];
    const float* bk    = (const float*)d_in[7];
    const float* Wv    = (const float*)d_in[8];
    const float* bv    = (const float*)d_in[9];
    const float* Wo    = (const float*)d_in[10];
    const float* bo    = (const float*)d_in[11];
    const float* gamma = (const float*)d_in[12];
    const float* beta  = (const float*)d_in[13];
    float* out = (float*)d_out;

    float *gQ, *gK, *gV, *gAO, *gP;
    cudaGetSymbolAddress((void**)&gQ,  g_Q);
    cudaGetSymbolAddress((void**)&gK,  g_K);
    cudaGetSymbolAddress((void**)&gV,  g_V);
    cudaGetSymbolAddress((void**)&gAO, g_AO);
    cudaGetSymbolAddress((void**)&gP,  g_P);

    cudaFuncSetAttribute(gemm_tc_kernel,
                         cudaFuncAttributeMaxDynamicSharedMemorySize,
                         GEMM_SMEM_BYTES);
    cudaFuncSetAttribute(attn_mma_kernel,
                         cudaFuncAttributeMaxDynamicSharedMemorySize,
                         ATTN_SMEM_BYTES);

    // QKV projections fused into one launch (z = 0,1,2)
    dim3 gqkv(MROWS / 128, 512 / 128, 3);
    gemm_tc_kernel<<<gqkv, 256, GEMM_SMEM_BYTES>>>(q, k, v, Wq, Wk, Wv,
                                                   bq, bk, bv, gQ, gK, gV);

    attn_mma_kernel<<<dim3(Ss / 128, Bb * Hh), 128, ATTN_SMEM_BYTES>>>(
        gQ, gK, gV, mask, gAO);

    // O projection (single instance)
    dim3 go(MROWS / 128, 512 / 128, 1);
    gemm_tc_kernel<<<go, 256, GEMM_SMEM_BYTES>>>(gAO, gAO, gAO, Wo, Wo, Wo,
                                                 bo, bo, bo, gP, gP, gP);

    ln_kernel<<<MROWS, 128>>>(q, gamma, beta, out);
}

// round 16
// speedup vs baseline: 1.7419x; 1.3826x over previous
#include <cuda_runtime.h>
#include <cuda_fp16.h>
#include <cstddef>
#include <cstdint>

#define Bb   4
#define Ss   2048
#define DIN  512
#define Hh   8
#define DM   512
#define MROWS (Bb*Ss)          // 8192

// Scratch (device globals: allocation-free rule)
__device__ float  g_Q [MROWS*DM];
__device__ __half g_K [MROWS*DM];
__device__ __half g_V [MROWS*DM];
__device__ float  g_AO[MROWS*DM];
__device__ float  g_P [MROWS*DIN];

// ===========================================================================
// helpers
// ===========================================================================
__device__ __forceinline__ uint32_t pack_h2(float lo, float hi) {
    uint32_t r;
    asm("cvt.rn.f16x2.f32 %0, %1, %2;" : "=r"(r) : "f"(hi), "f"(lo));
    return r;
}

// D += A * B  (m16n8k8, tf32 inputs, fp32 accum). row.col.
__device__ __forceinline__ void mma_tf32(float* d, const uint32_t* a,
                                         uint32_t b0, uint32_t b1) {
    asm volatile(
        "mma.sync.aligned.m16n8k8.row.col.f32.tf32.tf32.f32 "
        "{%0,%1,%2,%3}, {%4,%5,%6,%7}, {%8,%9}, {%0,%1,%2,%3};"
        : "+f"(d[0]), "+f"(d[1]), "+f"(d[2]), "+f"(d[3])
        : "r"(a[0]), "r"(a[1]), "r"(a[2]), "r"(a[3]), "r"(b0), "r"(b1));
}

// D += A * B  (m16n8k16, fp16 inputs, fp32 accum). row.col.
__device__ __forceinline__ void mma_f16(float* d, const uint32_t* a,
                                        uint32_t b0, uint32_t b1) {
    asm volatile(
        "mma.sync.aligned.m16n8k16.row.col.f32.f16.f16.f32 "
        "{%0,%1,%2,%3}, {%4,%5,%6,%7}, {%8,%9}, {%0,%1,%2,%3};"
        : "+f"(d[0]), "+f"(d[1]), "+f"(d[2]), "+f"(d[3])
        : "r"(a[0]), "r"(a[1]), "r"(a[2]), "r"(a[3]), "r"(b0), "r"(b1));
}

__device__ __forceinline__ void ldsm_x4(uint32_t* r, uint32_t addr) {
    asm volatile("ldmatrix.sync.aligned.m8n8.x4.shared.b16 {%0,%1,%2,%3}, [%4];"
                 : "=r"(r[0]), "=r"(r[1]), "=r"(r[2]), "=r"(r[3]) : "r"(addr));
}
__device__ __forceinline__ void ldsm_x4_t(uint32_t* r, uint32_t addr) {
    asm volatile("ldmatrix.sync.aligned.m8n8.x4.trans.shared.b16 {%0,%1,%2,%3}, [%4];"
                 : "=r"(r[0]), "=r"(r[1]), "=r"(r[2]), "=r"(r[3]) : "r"(addr));
}

__device__ __forceinline__ void cp_async16(uint32_t dst, const void* src) {
    asm volatile("cp.async.cg.shared.global [%0], [%1], 16;"
                 :: "r"(dst), "l"(src) : "memory");
}
#define CP_COMMIT() asm volatile("cp.async.commit_group;" ::: "memory")
#define CP_WAIT0()  asm volatile("cp.async.wait_group 0;" ::: "memory")
#define CP_WAIT1()  asm volatile("cp.async.wait_group 1;" ::: "memory")

// ===========================================================================
// Tensor-core GEMM, cp.async double-buffered (proven R15). gridDim.z selects
// up to 3 instances. hmask bit z => write fp16 output (for K/V projections).
// ===========================================================================
#define XS_STR 36
#define WS_STR 136
#define GEMM_STAGE_FLOATS (128*XS_STR + 32*WS_STR)      // 8960
#define GEMM_SMEM_BYTES (2 * GEMM_STAGE_FLOATS * 4)     // 71680

__global__ __launch_bounds__(256)
void gemm_tc_kernel(const float* __restrict__ X0, const float* __restrict__ X1,
                    const float* __restrict__ X2,
                    const float* __restrict__ W0, const float* __restrict__ W1,
                    const float* __restrict__ W2,
                    const float* __restrict__ b0p, const float* __restrict__ b1p,
                    const float* __restrict__ b2p,
                    void* __restrict__ C0v, void* __restrict__ C1v,
                    void* __restrict__ C2v, int hmask) {
    extern __shared__ float gsm[];

    const int z = blockIdx.z;
    const float* X    = (z == 0) ? X0 : (z == 1) ? X1 : X2;
    const float* W    = (z == 0) ? W0 : (z == 1) ? W1 : W2;
    const float* bias = (z == 0) ? b0p : (z == 1) ? b1p : b2p;
    void*        Cv   = (z == 0) ? C0v : (z == 1) ? C1v : C2v;
    const bool   tohalf = (hmask >> z) & 1;

    const int tid  = threadIdx.x;
    const int lane = tid & 31;
    const int wid  = tid >> 5;
    const int gid  = lane >> 2;
    const int tig  = lane & 3;

    const int warp_m = wid >> 2;
    const int warp_n = wid & 3;
    const int m_base = warp_m * 64;
    const int n_base = warp_n * 32;

    const int bm = blockIdx.x * 128;
    const int bn = blockIdx.y * 128;

    const uint32_t gsm_u = (uint32_t)__cvta_generic_to_shared(gsm);

    auto issue_stage = [&](int k0, int s) {
        const uint32_t Xs_u = gsm_u + 4u * (s * GEMM_STAGE_FLOATS);
        const uint32_t Ws_u = Xs_u + 4u * (128 * XS_STR);
        #pragma unroll
        for (int l = 0; l < 4; l++) {
            int e = tid + l * 256;
            int r = e >> 3, c4 = e & 7;
            cp_async16(Xs_u + 4u * (r * XS_STR + c4 * 4),
                       X + (size_t)(bm + r) * 512 + k0 + c4 * 4);
        }
        #pragma unroll
        for (int l = 0; l < 4; l++) {
            int e = tid + l * 256;
            int r = e >> 5, c4 = e & 31;
            cp_async16(Ws_u + 4u * (r * WS_STR + c4 * 4),
                       W + (size_t)(k0 + r) * 512 + bn + c4 * 4);
        }
        CP_COMMIT();
    };

    float acc[4][4][4];
    #pragma unroll
    for (int mf = 0; mf < 4; mf++)
        #pragma unroll
        for (int nf = 0; nf < 4; nf++)
            #pragma unroll
            for (int c = 0; c < 4; c++) acc[mf][nf][c] = 0.f;

    issue_stage(0, 0);

    for (int it = 0; it < 16; it++) {
        const int buf = it & 1;
        const float* Xs = gsm + buf * GEMM_STAGE_FLOATS;
        const float* Ws = Xs + 128 * XS_STR;

        CP_WAIT0();
        __syncthreads();
        if (it < 15) issue_stage((it + 1) * 32, buf ^ 1);

        #pragma unroll
        for (int ks = 0; ks < 4; ks++) {
            const int kk = ks * 8;
            uint32_t A[4][4];
            #pragma unroll
            for (int mf = 0; mf < 4; mf++) {
                const float* ap = Xs + (m_base + mf * 16 + gid) * XS_STR + kk + tig;
                A[mf][0] = __float_as_uint(ap[0]);
                A[mf][1] = __float_as_uint(ap[8 * XS_STR]);
                A[mf][2] = __float_as_uint(ap[4]);
                A[mf][3] = __float_as_uint(ap[8 * XS_STR + 4]);
            }
            #pragma unroll
            for (int nf = 0; nf < 4; nf++) {
                const float* bp = Ws + (kk + tig) * WS_STR + n_base + nf * 8 + gid;
                uint32_t bb0 = __float_as_uint(bp[0]);
                uint32_t bb1 = __float_as_uint(bp[4 * WS_STR]);
                #pragma unroll
                for (int mf = 0; mf < 4; mf++)
                    mma_tf32(acc[mf][nf], A[mf], bb0, bb1);
            }
        }
    }

    #pragma unroll
    for (int nf = 0; nf < 4; nf++) {
        const int col = bn + n_base + nf * 8 + 2 * tig;
        float2 b2 = *(const float2*)(bias + col);
        #pragma unroll
        for (int mf = 0; mf < 4; mf++) {
            const int row0 = bm + m_base + mf * 16 + gid;
            float o00 = acc[mf][nf][0] + b2.x, o01 = acc[mf][nf][1] + b2.y;
            float o10 = acc[mf][nf][2] + b2.x, o11 = acc[mf][nf][3] + b2.y;
            if (tohalf) {
                __half* C = (__half*)Cv;
                *(uint32_t*)(C + (size_t)row0 * 512 + col)       = pack_h2(o00, o01);
                *(uint32_t*)(C + (size_t)(row0 + 8) * 512 + col) = pack_h2(o10, o11);
            } else {
                float* C = (float*)Cv;
                float2 a = {o00, o01}, b = {o10, o11};
                *(float2*)(C + (size_t)row0 * 512 + col) = a;
                *(float2*)(C + (size_t)(row0 + 8) * 512 + col) = b;
            }
        }
    }
}

// ===========================================================================
// fp16 flash attention (m16n8k16). 1 CTA = (b,h), 128 q-rows, 4 warps x 32.
// K/V arrive fp16 from projection GEMMs via 3-stage cp.async pipeline.
// K B-frags: ldmatrix; V B-frags: ldmatrix.trans. P packs in-thread from the
// S C-fragment (layouts match) -> no shuffle transpose.
// Smem rows 144B (9x16B) -> conflict-free ldsm.
// ===========================================================================
#define KROWB 144                                   // bytes per 64-half row
#define ATTN_STAGE_BYTES (2 * 32 * KROWB)           // K + V = 9216
#define ATTN_SMEM_BYTES  (3 * ATTN_STAGE_BYTES)     // 27648

__global__ __launch_bounds__(128, 2)
void attn_mma_kernel(const float* __restrict__ Qg, const __half* __restrict__ Kg,
                     const __half* __restrict__ Vg, const float* __restrict__ mask,
                     float* __restrict__ AO) {
    extern __shared__ char smc[];
    const int tid  = threadIdx.x;
    const int lane = tid & 31;
    const int wid  = tid >> 5;        // 0..3
    const int gid  = lane >> 2;
    const int tig  = lane & 3;

    const uint32_t sm_u = (uint32_t)__cvta_generic_to_shared(smc);
    // ldsm lane bases (bytes)
    const uint32_t lmK = (uint32_t)((lane & 7) * KROWB + ((lane >> 3) & 3) * 16);
    const uint32_t lmV = (uint32_t)(((((lane >> 3) & 1) * 8) + (lane & 7)) * KROWB
                                    + (lane >> 4) * 16);

    const int bh = blockIdx.y;
    const int b  = bh >> 3;
    const int h  = bh & 7;
    const int q0 = blockIdx.x * 128;

    const __half* Kb = Kg + (size_t)b * Ss * 512 + h * 64;
    const __half* Vb = Vg + (size_t)b * Ss * 512 + h * 64;

    // cp.async coordinates: 2 K chunks + 2 V chunks per thread per tile
    auto load_kv_async = [&](int k0, int stage) {
        const uint32_t Ks = sm_u + (uint32_t)(stage * ATTN_STAGE_BYTES);
        const uint32_t Vs = Ks + 32 * KROWB;
        #pragma unroll
        for (int l = 0; l < 2; l++) {
            int idx = tid + l * 128;          // 0..255
            int r = idx >> 3, c = idx & 7;    // 32 rows x 8 chunks
            cp_async16(Ks + (uint32_t)(r * KROWB + c * 16),
                       Kb + (size_t)(k0 + r) * 512 + c * 8);
            cp_async16(Vs + (uint32_t)(r * KROWB + c * 16),
                       Vb + (size_t)(k0 + r) * 512 + c * 8);
        }
        CP_COMMIT();
    };

    load_kv_async(0, 0);
    load_kv_async(32, 1);

    // persistent Q A-fragments (fp16, pre-scaled 1/8): Qa[mf][kchunk][4]
    const int qrow0 = q0 + wid * 32 + gid;
    const int qrow1 = qrow0 + 16;
    uint32_t Qa[2][4][4];
    #pragma unroll
    for (int mf = 0; mf < 2; mf++) {
        const float* Qp = Qg + ((size_t)b * Ss + (mf ? qrow1 : qrow0)) * 512 + h * 64;
        const float* Qp8 = Qp + (size_t)8 * 512;
        #pragma unroll
        for (int kc = 0; kc < 4; kc++) {
            const int c0 = kc * 16 + 2 * tig;
            Qa[mf][kc][0] = pack_h2(Qp [c0] * 0.125f,     Qp [c0 + 1] * 0.125f);
            Qa[mf][kc][1] = pack_h2(Qp8[c0] * 0.125f,     Qp8[c0 + 1] * 0.125f);
            Qa[mf][kc][2] = pack_h2(Qp [c0 + 8] * 0.125f, Qp [c0 + 9] * 0.125f);
            Qa[mf][kc][3] = pack_h2(Qp8[c0 + 8] * 0.125f, Qp8[c0 + 9] * 0.125f);
        }
    }

    const float* Mr[4];
    Mr[0] = mask + (size_t)b * Ss * Ss + (size_t)qrow0 * Ss;
    Mr[1] = Mr[0] + (size_t)8 * Ss;
    Mr[2] = mask + (size_t)b * Ss * Ss + (size_t)qrow1 * Ss;
    Mr[3] = Mr[2] + (size_t)8 * Ss;

    float mI[4] = {-1e30f, -1e30f, -1e30f, -1e30f};
    float lI[4] = {0.f, 0.f, 0.f, 0.f};
    float O[2][8][4];
    #pragma unroll
    for (int mf = 0; mf < 2; mf++)
        #pragma unroll
        for (int j = 0; j < 8; j++)
            #pragma unroll
            for (int c = 0; c < 4; c++) O[mf][j][c] = 0.f;

    int stage = 0;
    for (int kt = 0; kt < 64; kt++) {
        const int k0 = kt * 32;
        const uint32_t Ks_u = sm_u + (uint32_t)(stage * ATTN_STAGE_BYTES);
        const uint32_t Vs_u = Ks_u + 32 * KROWB;

        CP_WAIT1();
        __syncthreads();
        if (kt < 62) load_kv_async(k0 + 64, (stage + 2) % 3);

        float2 mk[4][4];
        #pragma unroll
        for (int r = 0; r < 4; r++)
            #pragma unroll
            for (int kf = 0; kf < 4; kf++)
                mk[r][kf] = *(const float2*)(Mr[r] + k0 + kf * 8 + 2 * tig);

        // ---- S = Q K^T : fp16 m16n8k16, 8 ldsm per tile ----
        float S[2][4][4];
        #pragma unroll
        for (int mf = 0; mf < 2; mf++)
            #pragma unroll
            for (int kf = 0; kf < 4; kf++)
                #pragma unroll
                for (int c = 0; c < 4; c++) S[mf][kf][c] = 0.f;

        #pragma unroll
        for (int kf = 0; kf < 4; kf++) {
            #pragma unroll
            for (int p = 0; p < 2; p++) {
                uint32_t r[4];
                ldsm_x4(r, Ks_u + (uint32_t)(kf * 8 * KROWB + p * 64) + lmK);
                mma_f16(S[0][kf], Qa[0][2 * p],     r[0], r[1]);
                mma_f16(S[0][kf], Qa[0][2 * p + 1], r[2], r[3]);
                mma_f16(S[1][kf], Qa[1][2 * p],     r[0], r[1]);
                mma_f16(S[1][kf], Qa[1][2 * p + 1], r[2], r[3]);
            }
        }

        // ---- mask * s, threshold, online softmax ----
        #pragma unroll
        for (int mf = 0; mf < 2; mf++) {
            const int rA = mf * 2, rB = mf * 2 + 1;
            float mx0 = mI[rA], mx1 = mI[rB];
            #pragma unroll
            for (int kf = 0; kf < 4; kf++) {
                float s0 = S[mf][kf][0] * mk[rA][kf].x;
                float s1 = S[mf][kf][1] * mk[rA][kf].y;
                float s2 = S[mf][kf][2] * mk[rB][kf].x;
                float s3 = S[mf][kf][3] * mk[rB][kf].y;
                s0 = (s0 > 0.f) ? s0 : -10000.f;
                s1 = (s1 > 0.f) ? s1 : -10000.f;
                s2 = (s2 > 0.f) ? s2 : -10000.f;
                s3 = (s3 > 0.f) ? s3 : -10000.f;
                S[mf][kf][0] = s0; S[mf][kf][1] = s1;
                S[mf][kf][2] = s2; S[mf][kf][3] = s3;
                mx0 = fmaxf(mx0, fmaxf(s0, s1));
                mx1 = fmaxf(mx1, fmaxf(s2, s3));
            }
            mx0 = fmaxf(mx0, __shfl_xor_sync(0xffffffffu, mx0, 1));
            mx0 = fmaxf(mx0, __shfl_xor_sync(0xffffffffu, mx0, 2));
            mx1 = fmaxf(mx1, __shfl_xor_sync(0xffffffffu, mx1, 1));
            mx1 = fmaxf(mx1, __shfl_xor_sync(0xffffffffu, mx1, 2));

            float f0 = __expf(mI[rA] - mx0);
            float f1 = __expf(mI[rB] - mx1);
            float sum0 = 0.f, sum1 = 0.f;
            #pragma unroll
            for (int kf = 0; kf < 4; kf++) {
                float p0 = __expf(S[mf][kf][0] - mx0);
                float p1 = __expf(S[mf][kf][1] - mx0);
                float p2 = __expf(S[mf][kf][2] - mx1);
                float p3 = __expf(S[mf][kf][3] - mx1);
                sum0 += p0 + p1;
                sum1 += p2 + p3;
                S[mf][kf][0] = p0; S[mf][kf][1] = p1;
                S[mf][kf][2] = p2; S[mf][kf][3] = p3;
            }
            sum0 += __shfl_xor_sync(0xffffffffu, sum0, 1);
            sum0 += __shfl_xor_sync(0xffffffffu, sum0, 2);
            sum1 += __shfl_xor_sync(0xffffffffu, sum1, 1);
            sum1 += __shfl_xor_sync(0xffffffffu, sum1, 2);

            lI[rA] = lI[rA] * f0 + sum0;  mI[rA] = mx0;
            lI[rB] = lI[rB] * f1 + sum1;  mI[rB] = mx1;

            #pragma unroll
            for (int j = 0; j < 8; j++) {
                O[mf][j][0] *= f0; O[mf][j][1] *= f0;
                O[mf][j][2] *= f1; O[mf][j][3] *= f1;
            }
        }

        // ---- O += P @ V : A packed in-thread (C layout == A layout) ----
        #pragma unroll
        for (int c = 0; c < 2; c++) {              // key chunk of 16
            uint32_t A[2][4];
            #pragma unroll
            for (int mf = 0; mf < 2; mf++) {
                A[mf][0] = pack_h2(S[mf][2*c][0],     S[mf][2*c][1]);
                A[mf][1] = pack_h2(S[mf][2*c][2],     S[mf][2*c][3]);
                A[mf][2] = pack_h2(S[mf][2*c + 1][0], S[mf][2*c + 1][1]);
                A[mf][3] = pack_h2(S[mf][2*c + 1][2], S[mf][2*c + 1][3]);
            }
            #pragma unroll
            for (int dfp = 0; dfp < 4; dfp++) {    // df pairs
                uint32_t r[4];
                ldsm_x4_t(r, Vs_u + (uint32_t)(c * 16 * KROWB + dfp * 32) + lmV);
                mma_f16(O[0][2 * dfp],     A[0], r[0], r[1]);
                mma_f16(O[0][2 * dfp + 1], A[0], r[2], r[3]);
                mma_f16(O[1][2 * dfp],     A[1], r[0], r[1]);
                mma_f16(O[1][2 * dfp + 1], A[1], r[2], r[3]);
            }
        }

        stage = (stage + 1) % 3;
    }

    #pragma unroll
    for (int mf = 0; mf < 2; mf++) {
        const int rA = mf * 2, rB = mf * 2 + 1;
        const float inv0 = 1.f / lI[rA];
        const float inv1 = 1.f / lI[rB];
        float* Op0 = AO + ((size_t)b * Ss + (mf ? qrow1 : qrow0)) * 512 + h * 64;
        float* Op1 = Op0 + (size_t)8 * 512;
        #pragma unroll
        for (int df = 0; df < 8; df++) {
            float2 o0 = { O[mf][df][0] * inv0, O[mf][df][1] * inv0 };
            float2 o1 = { O[mf][df][2] * inv1, O[mf][df][3] * inv1 };
            *(float2*)(Op0 + df * 8 + 2 * tig) = o0;
            *(float2*)(Op1 + df * 8 + 2 * tig) = o1;
        }
    }
}

// ===========================================================================
// Residual + LayerNorm: 128 threads x float4 per 512-wide row (proven R10).
// ===========================================================================
__global__ __launch_bounds__(128)
void ln_kernel(const float* __restrict__ q, const float* __restrict__ gamma,
               const float* __restrict__ beta, float* __restrict__ out) {
    __shared__ float rs[4], rs2[4];
    const int r = blockIdx.x;
    const int j = threadIdx.x;          // 0..127
    const int w = j >> 5, ln = j & 31;

    float4 qv = *(const float4*)(q + (size_t)r * 512 + j * 4);
    float4 pv = *(const float4*)(g_P + (size_t)r * 512 + j * 4);
    float4 v  = { qv.x + pv.x, qv.y + pv.y, qv.z + pv.z, qv.w + pv.w };

    float s  = v.x + v.y + v.z + v.w;
    float s2 = v.x * v.x + v.y * v.y + v.z * v.z + v.w * v.w;
    #pragma unroll
    for (int o = 16; o > 0; o >>= 1) {
        s  += __shfl_xor_sync(0xffffffffu, s,  o);
        s2 += __shfl_xor_sync(0xffffffffu, s2, o);
    }
    if (ln == 0) { rs[w] = s; rs2[w] = s2; }
    __syncthreads();
    s  = rs[0]  + rs[1]  + rs[2]  + rs[3];
    s2 = rs2[0] + rs2[1] + rs2[2] + rs2[3];

    const float mu  = s * (1.f / 512.f);
    const float var = s2 * (1.f / 512.f) - mu * mu;
    const float inv = rsqrtf(var + 1e-5f);

    float4 g4 = *(const float4*)(gamma + j * 4);
    float4 b4 = *(const float4*)(beta + j * 4);
    float4 o;
    o.x = (v.x - mu) * inv * g4.x + b4.x;
    o.y = (v.y - mu) * inv * g4.y + b4.y;
    o.z = (v.z - mu) * inv * g4.z + b4.z;
    o.w = (v.w - mu) * inv * g4.w + b4.w;
    *(float4*)(out + (size_t)r * 512 + j * 4) = o;
}

// ===========================================================================
extern "C" void kernel_launch(void* const* d_in, const int* in_sizes, int n_in,
                              void* d_out, int out_size) {
    const float* q     = (const float*)d_in[0];
    const float* k     = (const float*)d_in[1];
    const float* v     = (const float*)d_in[2];
    const float* mask  = (const float*)d_in[3];
    const float* Wq    = (const float*)d_in[4];
    const float* bq    = (const float*)d_in[5];
    const float* Wk    = (const float*)d_in[6];
    const float* bk    = (const float*)d_in[7];
    const float* Wv    = (const float*)d_in[8];
    const float* bv    = (const float*)d_in[9];
    const float* Wo    = (const float*)d_in[10];
    const float* bo    = (const float*)d_in[11];
    const float* gamma = (const float*)d_in[12];
    const float* beta  = (const float*)d_in[13];
    float* out = (float*)d_out;

    float *gQ, *gAO, *gP;
    __half *gK, *gV;
    cudaGetSymbolAddress((void**)&gQ,  g_Q);
    cudaGetSymbolAddress((void**)&gK,  g_K);
    cudaGetSymbolAddress((void**)&gV,  g_V);
    cudaGetSymbolAddress((void**)&gAO, g_AO);
    cudaGetSymbolAddress((void**)&gP,  g_P);

    cudaFuncSetAttribute(gemm_tc_kernel,
                         cudaFuncAttributeMaxDynamicSharedMemorySize,
                         GEMM_SMEM_BYTES);
    cudaFuncSetAttribute(attn_mma_kernel,
                         cudaFuncAttributeMaxDynamicSharedMemorySize,
                         ATTN_SMEM_BYTES);

    // QKV projections fused into one launch (z=0 fp32 Q, z=1,2 fp16 K/V)
    dim3 gqkv(MROWS / 128, 512 / 128, 3);
    gemm_tc_kernel<<<gqkv, 256, GEMM_SMEM_BYTES>>>(q, k, v, Wq, Wk, Wv,
                                                   bq, bk, bv,
                                                   gQ, gK, gV, /*hmask=*/6);

    attn_mma_kernel<<<dim3(Ss / 128, Bb * Hh), 128, ATTN_SMEM_BYTES>>>(
        gQ, gK, gV, mask, gAO);

    // O projection (fp32 output)
    dim3 go(MROWS / 128, 512 / 128, 1);
    gemm_tc_kernel<<<go, 256, GEMM_SMEM_BYTES>>>(gAO, gAO, gAO, Wo, Wo, Wo,
                                                 bo, bo, bo,
                                                 gP, gP, gP, /*hmask=*/0);

    ln_kernel<<<MROWS, 128>>>(q, gamma, beta, out);
}

// round 17
// speedup vs baseline: 2.0249x; 1.1624x over previous
#include <cuda_runtime.h>
#include <cuda_fp16.h>
#include <cstddef>
#include <cstdint>

#define Bb   4
#define Ss   2048
#define DIN  512
#define Hh   8
#define DM   512
#define MROWS (Bb*Ss)          // 8192

// Scratch (device globals: allocation-free rule)
__device__ float  g_Q  [MROWS*DM];
__device__ __half g_K  [MROWS*DM];
__device__ __half g_V  [MROWS*DM];
__device__ __half g_AOh[MROWS*DM];
__device__ float  g_P  [MROWS*DIN];
__device__ __half g_qh [MROWS*DIN];
__device__ __half g_kh [MROWS*DIN];
__device__ __half g_vh [MROWS*DIN];
__device__ __half g_Wqh[DIN*DM];
__device__ __half g_Wkh[DIN*DM];
__device__ __half g_Wvh[DIN*DM];
__device__ __half g_Woh[DM*DIN];

// ===========================================================================
// helpers
// ===========================================================================
__device__ __forceinline__ uint32_t pack_h2(float lo, float hi) {
    uint32_t r;
    asm("cvt.rn.f16x2.f32 %0, %1, %2;" : "=r"(r) : "f"(hi), "f"(lo));
    return r;
}

// D += A * B  (m16n8k16, fp16 inputs, fp32 accum). row.col.
__device__ __forceinline__ void mma_f16(float* d, const uint32_t* a,
                                        uint32_t b0, uint32_t b1) {
    asm volatile(
        "mma.sync.aligned.m16n8k16.row.col.f32.f16.f16.f32 "
        "{%0,%1,%2,%3}, {%4,%5,%6,%7}, {%8,%9}, {%0,%1,%2,%3};"
        : "+f"(d[0]), "+f"(d[1]), "+f"(d[2]), "+f"(d[3])
        : "r"(a[0]), "r"(a[1]), "r"(a[2]), "r"(a[3]), "r"(b0), "r"(b1));
}

__device__ __forceinline__ void ldsm_x4(uint32_t* r, uint32_t addr) {
    asm volatile("ldmatrix.sync.aligned.m8n8.x4.shared.b16 {%0,%1,%2,%3}, [%4];"
                 : "=r"(r[0]), "=r"(r[1]), "=r"(r[2]), "=r"(r[3]) : "r"(addr));
}
__device__ __forceinline__ void ldsm_x4_t(uint32_t* r, uint32_t addr) {
    asm volatile("ldmatrix.sync.aligned.m8n8.x4.trans.shared.b16 {%0,%1,%2,%3}, [%4];"
                 : "=r"(r[0]), "=r"(r[1]), "=r"(r[2]), "=r"(r[3]) : "r"(addr));
}

__device__ __forceinline__ void cp_async16(uint32_t dst, const void* src) {
    asm volatile("cp.async.cg.shared.global [%0], [%1], 16;"
                 :: "r"(dst), "l"(src) : "memory");
}
#define CP_COMMIT() asm volatile("cp.async.commit_group;" ::: "memory")
#define CP_WAIT0()  asm volatile("cp.async.wait_group 0;" ::: "memory")
#define CP_WAIT1()  asm volatile("cp.async.wait_group 1;" ::: "memory")

// ===========================================================================
// fp32 -> fp16 conversion (up to 4 tensors per launch via gridDim.z)
// ===========================================================================
__global__ __launch_bounds__(256)
void cvt_f2h_kernel(const float* __restrict__ s0, const float* __restrict__ s1,
                    const float* __restrict__ s2, const float* __restrict__ s3,
                    __half* __restrict__ d0, __half* __restrict__ d1,
                    __half* __restrict__ d2, __half* __restrict__ d3, int n4) {
    const int z = blockIdx.z;
    const float* s = (z == 0) ? s0 : (z == 1) ? s1 : (z == 2) ? s2 : s3;
    __half*      d = (z == 0) ? d0 : (z == 1) ? d1 : (z == 2) ? d2 : d3;
    int i = blockIdx.x * 256 + threadIdx.x;
    if (i < n4) {
        float4 v = ((const float4*)s)[i];
        uint2 o = { pack_h2(v.x, v.y), pack_h2(v.z, v.w) };
        ((uint2*)d)[i] = o;
    }
}

// ===========================================================================
// fp16 tensor-core GEMM: C[M,512] = X[M,512] @ W[512,512] + bias.
// BM=128, BN=128, BK=64, cp.async double-buffered, 256 threads, 2 CTAs/SM.
// A-frags: ldmatrix on [m][k] (row stride 144B); B-frags: ldmatrix.trans on
// [k][n] (row stride 272B) -- both patterns proven in the R16 attention kernel.
// gridDim.z selects up to 3 instances; hmask bit z => fp16 output.
// ===========================================================================
#define XB 144
#define WB 272
#define G16_STAGE_BYTES (128*XB + 64*WB)     // 35840
#define G16_SMEM_BYTES  (2 * G16_STAGE_BYTES) // 71680

__global__ __launch_bounds__(256)
void gemm_f16_kernel(const __half* __restrict__ X0, const __half* __restrict__ X1,
                     const __half* __restrict__ X2,
                     const __half* __restrict__ W0, const __half* __restrict__ W1,
                     const __half* __restrict__ W2,
                     const float* __restrict__ b0p, const float* __restrict__ b1p,
                     const float* __restrict__ b2p,
                     void* __restrict__ C0v, void* __restrict__ C1v,
                     void* __restrict__ C2v, int hmask) {
    extern __shared__ char gsmc[];

    const int z = blockIdx.z;
    const __half* X    = (z == 0) ? X0 : (z == 1) ? X1 : X2;
    const __half* W    = (z == 0) ? W0 : (z == 1) ? W1 : W2;
    const float*  bias = (z == 0) ? b0p : (z == 1) ? b1p : b2p;
    void*         Cv   = (z == 0) ? C0v : (z == 1) ? C1v : C2v;
    const bool    tohalf = (hmask >> z) & 1;

    const int tid  = threadIdx.x;
    const int lane = tid & 31;
    const int wid  = tid >> 5;
    const int gid  = lane >> 2;
    const int tig  = lane & 3;

    const int m_base = (wid >> 2) * 64;
    const int n_base = (wid & 3) * 32;

    const int bm = blockIdx.x * 128;
    const int bn = blockIdx.y * 128;

    const uint32_t gsm_u = (uint32_t)__cvta_generic_to_shared(gsmc);
    const uint32_t lmA = (uint32_t)((lane & 15) * XB + (lane >> 4) * 16);
    const uint32_t lmW = (uint32_t)(((((lane >> 3) & 1) * 8) + (lane & 7)) * WB
                                    + (lane >> 4) * 16);

    auto issue_stage = [&](int k0, int s) {
        const uint32_t Xs_u = gsm_u + (uint32_t)(s * G16_STAGE_BYTES);
        const uint32_t Ws_u = Xs_u + 128 * XB;
        #pragma unroll
        for (int l = 0; l < 4; l++) {
            int idx = tid + l * 256;           // 0..1023
            int r = idx >> 3, c = idx & 7;     // X: 128 rows x 8 chunks
            cp_async16(Xs_u + (uint32_t)(r * XB + c * 16),
                       X + (size_t)(bm + r) * 512 + k0 + c * 8);
        }
        #pragma unroll
        for (int l = 0; l < 4; l++) {
            int idx = tid + l * 256;
            int r = idx >> 4, c = idx & 15;    // W: 64 rows x 16 chunks
            cp_async16(Ws_u + (uint32_t)(r * WB + c * 16),
                       W + (size_t)(k0 + r) * 512 + bn + c * 8);
        }
        CP_COMMIT();
    };

    float acc[4][4][4];
    #pragma unroll
    for (int mf = 0; mf < 4; mf++)
        #pragma unroll
        for (int nf = 0; nf < 4; nf++)
            #pragma unroll
            for (int c = 0; c < 4; c++) acc[mf][nf][c] = 0.f;

    issue_stage(0, 0);

    for (int it = 0; it < 8; it++) {
        const int buf = it & 1;
        const uint32_t Xs_u = gsm_u + (uint32_t)(buf * G16_STAGE_BYTES);
        const uint32_t Ws_u = Xs_u + 128 * XB;

        CP_WAIT0();
        __syncthreads();
        if (it < 7) issue_stage((it + 1) * 64, buf ^ 1);

        #pragma unroll
        for (int kc = 0; kc < 4; kc++) {
            uint32_t A[4][4];
            #pragma unroll
            for (int mf = 0; mf < 4; mf++)
                ldsm_x4(A[mf], Xs_u + (uint32_t)((m_base + mf * 16) * XB + kc * 32) + lmA);
            #pragma unroll
            for (int nf2 = 0; nf2 < 2; nf2++) {
                uint32_t r[4];
                ldsm_x4_t(r, Ws_u + (uint32_t)(kc * 16 * WB + (n_base + nf2 * 16) * 2) + lmW);
                #pragma unroll
                for (int mf = 0; mf < 4; mf++) {
                    mma_f16(acc[mf][2 * nf2],     A[mf], r[0], r[1]);
                    mma_f16(acc[mf][2 * nf2 + 1], A[mf], r[2], r[3]);
                }
            }
        }
    }

    #pragma unroll
    for (int nf = 0; nf < 4; nf++) {
        const int col = bn + n_base + nf * 8 + 2 * tig;
        float2 b2 = *(const float2*)(bias + col);
        #pragma unroll
        for (int mf = 0; mf < 4; mf++) {
            const int row0 = bm + m_base + mf * 16 + gid;
            float o00 = acc[mf][nf][0] + b2.x, o01 = acc[mf][nf][1] + b2.y;
            float o10 = acc[mf][nf][2] + b2.x, o11 = acc[mf][nf][3] + b2.y;
            if (tohalf) {
                __half* C = (__half*)Cv;
                *(uint32_t*)(C + (size_t)row0 * 512 + col)       = pack_h2(o00, o01);
                *(uint32_t*)(C + (size_t)(row0 + 8) * 512 + col) = pack_h2(o10, o11);
            } else {
                float* C = (float*)Cv;
                float2 a = {o00, o01}, b = {o10, o11};
                *(float2*)(C + (size_t)row0 * 512 + col) = a;
                *(float2*)(C + (size_t)(row0 + 8) * 512 + col) = b;
            }
        }
    }
}

// ===========================================================================
// fp16 flash attention (proven R16 body; epilogue now writes fp16 AO).
// ===========================================================================
#define KROWB 144
#define ATTN_STAGE_BYTES (2 * 32 * KROWB)           // 9216
#define ATTN_SMEM_BYTES  (3 * ATTN_STAGE_BYTES)     // 27648

__global__ __launch_bounds__(128, 2)
void attn_mma_kernel(const float* __restrict__ Qg, const __half* __restrict__ Kg,
                     const __half* __restrict__ Vg, const float* __restrict__ mask,
                     __half* __restrict__ AO) {
    extern __shared__ char smc[];
    const int tid  = threadIdx.x;
    const int lane = tid & 31;
    const int wid  = tid >> 5;        // 0..3
    const int gid  = lane >> 2;
    const int tig  = lane & 3;

    const uint32_t sm_u = (uint32_t)__cvta_generic_to_shared(smc);
    const uint32_t lmK = (uint32_t)((lane & 7) * KROWB + ((lane >> 3) & 3) * 16);
    const uint32_t lmV = (uint32_t)(((((lane >> 3) & 1) * 8) + (lane & 7)) * KROWB
                                    + (lane >> 4) * 16);

    const int bh = blockIdx.y;
    const int b  = bh >> 3;
    const int h  = bh & 7;
    const int q0 = blockIdx.x * 128;

    const __half* Kb = Kg + (size_t)b * Ss * 512 + h * 64;
    const __half* Vb = Vg + (size_t)b * Ss * 512 + h * 64;

    auto load_kv_async = [&](int k0, int stage) {
        const uint32_t Ks = sm_u + (uint32_t)(stage * ATTN_STAGE_BYTES);
        const uint32_t Vs = Ks + 32 * KROWB;
        #pragma unroll
        for (int l = 0; l < 2; l++) {
            int idx = tid + l * 128;
            int r = idx >> 3, c = idx & 7;
            cp_async16(Ks + (uint32_t)(r * KROWB + c * 16),
                       Kb + (size_t)(k0 + r) * 512 + c * 8);
            cp_async16(Vs + (uint32_t)(r * KROWB + c * 16),
                       Vb + (size_t)(k0 + r) * 512 + c * 8);
        }
        CP_COMMIT();
    };

    load_kv_async(0, 0);
    load_kv_async(32, 1);

    const int qrow0 = q0 + wid * 32 + gid;
    const int qrow1 = qrow0 + 16;
    uint32_t Qa[2][4][4];
    #pragma unroll
    for (int mf = 0; mf < 2; mf++) {
        const float* Qp = Qg + ((size_t)b * Ss + (mf ? qrow1 : qrow0)) * 512 + h * 64;
        const float* Qp8 = Qp + (size_t)8 * 512;
        #pragma unroll
        for (int kc = 0; kc < 4; kc++) {
            const int c0 = kc * 16 + 2 * tig;
            Qa[mf][kc][0] = pack_h2(Qp [c0] * 0.125f,     Qp [c0 + 1] * 0.125f);
            Qa[mf][kc][1] = pack_h2(Qp8[c0] * 0.125f,     Qp8[c0 + 1] * 0.125f);
            Qa[mf][kc][2] = pack_h2(Qp [c0 + 8] * 0.125f, Qp [c0 + 9] * 0.125f);
            Qa[mf][kc][3] = pack_h2(Qp8[c0 + 8] * 0.125f, Qp8[c0 + 9] * 0.125f);
        }
    }

    const float* Mr[4];
    Mr[0] = mask + (size_t)b * Ss * Ss + (size_t)qrow0 * Ss;
    Mr[1] = Mr[0] + (size_t)8 * Ss;
    Mr[2] = mask + (size_t)b * Ss * Ss + (size_t)qrow1 * Ss;
    Mr[3] = Mr[2] + (size_t)8 * Ss;

    float mI[4] = {-1e30f, -1e30f, -1e30f, -1e30f};
    float lI[4] = {0.f, 0.f, 0.f, 0.f};
    float O[2][8][4];
    #pragma unroll
    for (int mf = 0; mf < 2; mf++)
        #pragma unroll
        for (int j = 0; j < 8; j++)
            #pragma unroll
            for (int c = 0; c < 4; c++) O[mf][j][c] = 0.f;

    int stage = 0;
    for (int kt = 0; kt < 64; kt++) {
        const int k0 = kt * 32;
        const uint32_t Ks_u = sm_u + (uint32_t)(stage * ATTN_STAGE_BYTES);
        const uint32_t Vs_u = Ks_u + 32 * KROWB;

        CP_WAIT1();
        __syncthreads();
        if (kt < 62) load_kv_async(k0 + 64, (stage + 2) % 3);

        float2 mk[4][4];
        #pragma unroll
        for (int r = 0; r < 4; r++)
            #pragma unroll
            for (int kf = 0; kf < 4; kf++)
                mk[r][kf] = *(const float2*)(Mr[r] + k0 + kf * 8 + 2 * tig);

        float S[2][4][4];
        #pragma unroll
        for (int mf = 0; mf < 2; mf++)
            #pragma unroll
            for (int kf = 0; kf < 4; kf++)
                #pragma unroll
                for (int c = 0; c < 4; c++) S[mf][kf][c] = 0.f;

        #pragma unroll
        for (int kf = 0; kf < 4; kf++) {
            #pragma unroll
            for (int p = 0; p < 2; p++) {
                uint32_t r[4];
                ldsm_x4(r, Ks_u + (uint32_t)(kf * 8 * KROWB + p * 64) + lmK);
                mma_f16(S[0][kf], Qa[0][2 * p],     r[0], r[1]);
                mma_f16(S[0][kf], Qa[0][2 * p + 1], r[2], r[3]);
                mma_f16(S[1][kf], Qa[1][2 * p],     r[0], r[1]);
                mma_f16(S[1][kf], Qa[1][2 * p + 1], r[2], r[3]);
            }
        }

        #pragma unroll
        for (int mf = 0; mf < 2; mf++) {
            const int rA = mf * 2, rB = mf * 2 + 1;
            float mx0 = mI[rA], mx1 = mI[rB];
            #pragma unroll
            for (int kf = 0; kf < 4; kf++) {
                float s0 = S[mf][kf][0] * mk[rA][kf].x;
                float s1 = S[mf][kf][1] * mk[rA][kf].y;
                float s2 = S[mf][kf][2] * mk[rB][kf].x;
                float s3 = S[mf][kf][3] * mk[rB][kf].y;
                s0 = (s0 > 0.f) ? s0 : -10000.f;
                s1 = (s1 > 0.f) ? s1 : -10000.f;
                s2 = (s2 > 0.f) ? s2 : -10000.f;
                s3 = (s3 > 0.f) ? s3 : -10000.f;
                S[mf][kf][0] = s0; S[mf][kf][1] = s1;
                S[mf][kf][2] = s2; S[mf][kf][3] = s3;
                mx0 = fmaxf(mx0, fmaxf(s0, s1));
                mx1 = fmaxf(mx1, fmaxf(s2, s3));
            }
            mx0 = fmaxf(mx0, __shfl_xor_sync(0xffffffffu, mx0, 1));
            mx0 = fmaxf(mx0, __shfl_xor_sync(0xffffffffu, mx0, 2));
            mx1 = fmaxf(mx1, __shfl_xor_sync(0xffffffffu, mx1, 1));
            mx1 = fmaxf(mx1, __shfl_xor_sync(0xffffffffu, mx1, 2));

            float f0 = __expf(mI[rA] - mx0);
            float f1 = __expf(mI[rB] - mx1);
            float sum0 = 0.f, sum1 = 0.f;
            #pragma unroll
            for (int kf = 0; kf < 4; kf++) {
                float p0 = __expf(S[mf][kf][0] - mx0);
                float p1 = __expf(S[mf][kf][1] - mx0);
                float p2 = __expf(S[mf][kf][2] - mx1);
                float p3 = __expf(S[mf][kf][3] - mx1);
                sum0 += p0 + p1;
                sum1 += p2 + p3;
                S[mf][kf][0] = p0; S[mf][kf][1] = p1;
                S[mf][kf][2] = p2; S[mf][kf][3] = p3;
            }
            sum0 += __shfl_xor_sync(0xffffffffu, sum0, 1);
            sum0 += __shfl_xor_sync(0xffffffffu, sum0, 2);
            sum1 += __shfl_xor_sync(0xffffffffu, sum1, 1);
            sum1 += __shfl_xor_sync(0xffffffffu, sum1, 2);

            lI[rA] = lI[rA] * f0 + sum0;  mI[rA] = mx0;
            lI[rB] = lI[rB] * f1 + sum1;  mI[rB] = mx1;

            #pragma unroll
            for (int j = 0; j < 8; j++) {
                O[mf][j][0] *= f0; O[mf][j][1] *= f0;
                O[mf][j][2] *= f1; O[mf][j][3] *= f1;
            }
        }

        #pragma unroll
        for (int c = 0; c < 2; c++) {
            uint32_t A[2][4];
            #pragma unroll
            for (int mf = 0; mf < 2; mf++) {
                A[mf][0] = pack_h2(S[mf][2*c][0],     S[mf][2*c][1]);
                A[mf][1] = pack_h2(S[mf][2*c][2],     S[mf][2*c][3]);
                A[mf][2] = pack_h2(S[mf][2*c + 1][0], S[mf][2*c + 1][1]);
                A[mf][3] = pack_h2(S[mf][2*c + 1][2], S[mf][2*c + 1][3]);
            }
            #pragma unroll
            for (int dfp = 0; dfp < 4; dfp++) {
                uint32_t r[4];
                ldsm_x4_t(r, Vs_u + (uint32_t)(c * 16 * KROWB + dfp * 32) + lmV);
                mma_f16(O[0][2 * dfp],     A[0], r[0], r[1]);
                mma_f16(O[0][2 * dfp + 1], A[0], r[2], r[3]);
                mma_f16(O[1][2 * dfp],     A[1], r[0], r[1]);
                mma_f16(O[1][2 * dfp + 1], A[1], r[2], r[3]);
            }
        }

        stage = (stage + 1) % 3;
    }

    #pragma unroll
    for (int mf = 0; mf < 2; mf++) {
        const int rA = mf * 2, rB = mf * 2 + 1;
        const float inv0 = 1.f / lI[rA];
        const float inv1 = 1.f / lI[rB];
        __half* Op0 = AO + ((size_t)b * Ss + (mf ? qrow1 : qrow0)) * 512 + h * 64;
        __half* Op1 = Op0 + (size_t)8 * 512;
        #pragma unroll
        for (int df = 0; df < 8; df++) {
            *(uint32_t*)(Op0 + df * 8 + 2 * tig) =
                pack_h2(O[mf][df][0] * inv0, O[mf][df][1] * inv0);
            *(uint32_t*)(Op1 + df * 8 + 2 * tig) =
                pack_h2(O[mf][df][2] * inv1, O[mf][df][3] * inv1);
        }
    }
}

// ===========================================================================
// Residual + LayerNorm (proven R10).
// ===========================================================================
__global__ __launch_bounds__(128)
void ln_kernel(const float* __restrict__ q, const float* __restrict__ gamma,
               const float* __restrict__ beta, float* __restrict__ out) {
    __shared__ float rs[4], rs2[4];
    const int r = blockIdx.x;
    const int j = threadIdx.x;
    const int w = j >> 5, ln = j & 31;

    float4 qv = *(const float4*)(q + (size_t)r * 512 + j * 4);
    float4 pv = *(const float4*)(g_P + (size_t)r * 512 + j * 4);
    float4 v  = { qv.x + pv.x, qv.y + pv.y, qv.z + pv.z, qv.w + pv.w };

    float s  = v.x + v.y + v.z + v.w;
    float s2 = v.x * v.x + v.y * v.y + v.z * v.z + v.w * v.w;
    #pragma unroll
    for (int o = 16; o > 0; o >>= 1) {
        s  += __shfl_xor_sync(0xffffffffu, s,  o);
        s2 += __shfl_xor_sync(0xffffffffu, s2, o);
    }
    if (ln == 0) { rs[w] = s; rs2[w] = s2; }
    __syncthreads();
    s  = rs[0]  + rs[1]  + rs[2]  + rs[3];
    s2 = rs2[0] + rs2[1] + rs2[2] + rs2[3];

    const float mu  = s * (1.f / 512.f);
    const float var = s2 * (1.f / 512.f) - mu * mu;
    const float inv = rsqrtf(var + 1e-5f);

    float4 g4 = *(const float4*)(gamma + j * 4);
    float4 b4 = *(const float4*)(beta + j * 4);
    float4 o;
    o.x = (v.x - mu) * inv * g4.x + b4.x;
    o.y = (v.y - mu) * inv * g4.y + b4.y;
    o.z = (v.z - mu) * inv * g4.z + b4.z;
    o.w = (v.w - mu) * inv * g4.w + b4.w;
    *(float4*)(out + (size_t)r * 512 + j * 4) = o;
}

// ===========================================================================
extern "C" void kernel_launch(void* const* d_in, const int* in_sizes, int n_in,
                              void* d_out, int out_size) {
    const float* q     = (const float*)d_in[0];
    const float* k     = (const float*)d_in[1];
    const float* v     = (const float*)d_in[2];
    const float* mask  = (const float*)d_in[3];
    const float* Wq    = (const float*)d_in[4];
    const float* bq    = (const float*)d_in[5];
    const float* Wk    = (const float*)d_in[6];
    const float* bk    = (const float*)d_in[7];
    const float* Wv    = (const float*)d_in[8];
    const float* bv    = (const float*)d_in[9];
    const float* Wo    = (const float*)d_in[10];
    const float* bo    = (const float*)d_in[11];
    const float* gamma = (const float*)d_in[12];
    const float* beta  = (const float*)d_in[13];
    float* out = (float*)d_out;

    float *gQ, *gP;
    __half *gK, *gV, *gAOh, *gqh, *gkh, *gvh, *gWqh, *gWkh, *gWvh, *gWoh;
    cudaGetSymbolAddress((void**)&gQ,   g_Q);
    cudaGetSymbolAddress((void**)&gK,   g_K);
    cudaGetSymbolAddress((void**)&gV,   g_V);
    cudaGetSymbolAddress((void**)&gAOh, g_AOh);
    cudaGetSymbolAddress((void**)&gP,   g_P);
    cudaGetSymbolAddress((void**)&gqh,  g_qh);
    cudaGetSymbolAddress((void**)&gkh,  g_kh);
    cudaGetSymbolAddress((void**)&gvh,  g_vh);
    cudaGetSymbolAddress((void**)&gWqh, g_Wqh);
    cudaGetSymbolAddress((void**)&gWkh, g_Wkh);
    cudaGetSymbolAddress((void**)&gWvh, g_Wvh);
    cudaGetSymbolAddress((void**)&gWoh, g_Woh);

    cudaFuncSetAttribute(gemm_f16_kernel,
                         cudaFuncAttributeMaxDynamicSharedMemorySize,
                         G16_SMEM_BYTES);
    cudaFuncSetAttribute(attn_mma_kernel,
                         cudaFuncAttributeMaxDynamicSharedMemorySize,
                         ATTN_SMEM_BYTES);

    // fp32 -> fp16 conversions: inputs (z=0..2), weights (z=0..3)
    cvt_f2h_kernel<<<dim3((MROWS * DIN / 4 + 255) / 256, 1, 3), 256>>>(
        q, k, v, q, gqh, gkh, gvh, gqh, MROWS * DIN / 4);
    cvt_f2h_kernel<<<dim3((DIN * DM / 4 + 255) / 256, 1, 4), 256>>>(
        Wq, Wk, Wv, Wo, gWqh, gWkh, gWvh, gWoh, DIN * DM / 4);

    // QKV projections (z=0 Q fp32 out, z=1,2 K/V fp16 out)
    dim3 gqkv(MROWS / 128, 512 / 128, 3);
    gemm_f16_kernel<<<gqkv, 256, G16_SMEM_BYTES>>>(
        gqh, gkh, gvh, gWqh, gWkh, gWvh, bq, bk, bv, gQ, gK, gV, /*hmask=*/6);

    attn_mma_kernel<<<dim3(Ss / 128, Bb * Hh), 128, ATTN_SMEM_BYTES>>>(
        gQ, gK, gV, mask, gAOh);

    // O projection (fp16 in, fp32 out)
    dim3 go(MROWS / 128, 512 / 128, 1);
    gemm_f16_kernel<<<go, 256, G16_SMEM_BYTES>>>(
        gAOh, gAOh, gAOh, gWoh, gWoh, gWoh, bo, bo, bo, gP, gP, gP, /*hmask=*/0);

    ln_kernel<<<MROWS, 128>>>(q, gamma, beta, out);
}